// round 11
// baseline (speedup 1.0000x reference)
#include <cuda_runtime.h>
#include <cuda_bf16.h>
#include <math.h>
#include <stdint.h>
#include <string.h>

#define B_    2
#define DD    16
#define HH    14
#define WWQ   14
#define CDIM  768
#define SP    (DD*HH*WWQ)      /* 3136 */
#define NT    (B_*SP)          /* 6272 tokens */
#define NWIN  392
#define BW    16
#define HEADS 24
#define HD    32
#define RPB_SZ 2535

/* packed int8 weight element counts: [w0 | w1], row stride 2K */
#define EW_QKV  (2304u*1536u)
#define EW_PROJ (768u*1536u)
#define EW_FC1  (3072u*1536u)
#define EW_FC2  (768u*6144u)
#define EW_C1   (128u*1536u)

/* ---------------- scratch ---------------- */
__device__ float g_Xs [NT*CDIM];
__device__ float g_X  [2][NT*CDIM];
__device__ float g_QKV[2][NT*3*CDIM];
__device__ float g_AO [2][NT*CDIM];
__device__ float g_H  [2][(size_t)NT*3072];     /* H-pass buffer / fp32 hidden */
__device__ float g_T3 [2][NT*64];
__device__ float g_O  [2][NT*2];
__device__ int   g_map[2][NT];
__device__ float g_BiasE[4][(size_t)HEADS*NWIN*NWIN];
__device__ int8_t g_Wq [4*EW_QKV];
__device__ int8_t g_Wp [4*EW_PROJ];
__device__ int8_t g_Wf1[4*EW_FC1];
__device__ int8_t g_Wf2[4*EW_FC2];
__device__ int8_t g_Wc1[2*EW_C1];
__device__ float g_sWq [4*2304];
__device__ float g_sWp [4*768];
__device__ float g_sWf1[4*3072];
__device__ float g_sWf2[4*768];
__device__ float g_sWc1[2*128];
__device__ int8_t g_Ap [2][(size_t)NT*1536];
__device__ int8_t g_Ap2[2][(size_t)NT*6144];
__device__ float g_sA [2][NT];
__device__ float g_sA2[2][NT];

__device__ __forceinline__ float gelu_f(float x) {
    return 0.5f * x * (1.0f + erff(x * 0.70710678118654752f));
}
__device__ __forceinline__ uint32_t smem_u32(const void* p) {
    uint32_t a;
    asm("{ .reg .u64 t; cvta.to.shared.u64 t, %1; cvt.u32.u64 %0, t; }" : "=r"(a) : "l"(p));
    return a;
}
#define CP16(s, g) \
    asm volatile("cp.async.cg.shared.global [%0], [%1], 16;" :: "r"(s), "l"(g) : "memory")
#define CP_COMMIT() asm volatile("cp.async.commit_group;" ::: "memory")
#define CP_WAIT1()  asm volatile("cp.async.wait_group 1;" ::: "memory")
#define LDSM4(r, addr) \
    asm volatile("ldmatrix.sync.aligned.m8n8.x4.shared.b16 {%0,%1,%2,%3}, [%4];" \
        : "=r"((r)[0]), "=r"((r)[1]), "=r"((r)[2]), "=r"((r)[3]) : "r"(addr))
#define MMAS8(c, a, b0, b1) \
    asm volatile("mma.sync.aligned.m16n8k32.row.col.s32.s8.s8.s32 " \
        "{%0,%1,%2,%3}, {%4,%5,%6,%7}, {%8,%9}, {%0,%1,%2,%3};" \
        : "+r"((c)[0]), "+r"((c)[1]), "+r"((c)[2]), "+r"((c)[3]) \
        : "r"((a)[0]), "r"((a)[1]), "r"((a)[2]), "r"((a)[3]), "r"(b0), "r"(b1))
#define FMA2(d, a, b) \
    asm("fma.rn.f32x2 %0, %1, %2, %0;" : "+l"(d) : "l"(a), "l"(b))

/* block-wide reduce helpers (256 threads) */
__device__ __forceinline__ float blk_sum(float v, float* red, int tid) {
#pragma unroll
    for (int o = 16; o; o >>= 1) v += __shfl_xor_sync(0xffffffffu, v, o);
    if ((tid & 31) == 0) red[tid >> 5] = v;
    __syncthreads();
    if (tid < 32) {
        float t = (tid < 8) ? red[tid] : 0.f;
#pragma unroll
        for (int o = 4; o; o >>= 1) t += __shfl_xor_sync(0xffffffffu, t, o);
        if (tid == 0) red[0] = t;
    }
    __syncthreads();
    float r = red[0];
    __syncthreads();
    return r;
}
__device__ __forceinline__ float blk_max(float v, float* red, int tid) {
#pragma unroll
    for (int o = 16; o; o >>= 1) v = fmaxf(v, __shfl_xor_sync(0xffffffffu, v, o));
    if ((tid & 31) == 0) red[tid >> 5] = v;
    __syncthreads();
    if (tid < 32) {
        float t = (tid < 8) ? red[tid] : 0.f;
#pragma unroll
        for (int o = 4; o; o >>= 1) t = fmaxf(t, __shfl_xor_sync(0xffffffffu, t, o));
        if (tid == 0) red[0] = t;
    }
    __syncthreads();
    float r = red[0];
    __syncthreads();
    return r;
}
__device__ __forceinline__ void quant2(float q, int8_t* d0, int8_t* d1) {
    int a0 = __float2int_rn(q);
    int a1 = __float2int_rn((q - (float)a0) * 128.f);
    *d0 = (int8_t)a0;
    *d1 = (int8_t)a1;
}

/* ---------------- window/roll index maps ---------------- */
__global__ void init_maps_kernel() {
    int wt = blockIdx.x * blockDim.x + threadIdx.x;
    if (wt >= NT) return;
    int win = wt / NWIN, n = wt % NWIN;
    int b = win >> 3, wr = win & 7;
    int wd = wr >> 2, wh = (wr >> 1) & 1, ww = wr & 1;
    int d0 = n / 49, r = n % 49, h0 = r / 7, w0 = r % 7;
    for (int s = 0; s < 2; s++) {
        int sd = s ? 4 : 0, sh = s ? 3 : 0, sw = s ? 3 : 0;
        int gd = (wd * 8 + d0 + sd) & 15;
        int gh = (wh * 7 + h0 + sh) % 14;
        int gw = (ww * 7 + w0 + sw) % 14;
        g_map[s][wt] = ((b * DD + gd) * HH + gh) * WWQ + gw;
    }
}

/* ---------------- expand rel-pos bias ---------------- */
__global__ void bias_exp_kernel(const float* __restrict__ rpb, const int* __restrict__ rpi,
                                float* __restrict__ dst) {
    size_t idx = (size_t)blockIdx.x * 256 + threadIdx.x;
    if (idx >= (size_t)HEADS * NWIN * NWIN) return;
    int m = (int)(idx % NWIN);
    int rest = (int)(idx / NWIN);
    int n = rest % NWIN, h = rest / NWIN;
    dst[idx] = rpb[(size_t)rpi[n * NWIN + m] * HEADS + h];
}

/* ---------------- (B,C,D,H,W) -> (token, C) transpose ---------------- */
__global__ void transpose_in_kernel(const float* __restrict__ x, float* __restrict__ X) {
    __shared__ float tile[32][33];
    int b = blockIdx.z;
    int s0 = blockIdx.x * 32, c0 = blockIdx.y * 32;
    int tx = threadIdx.x, ty = threadIdx.y;
#pragma unroll
    for (int i = 0; i < 32; i += 8)
        tile[ty + i][tx] = x[((size_t)(b * CDIM + c0 + ty + i)) * SP + s0 + tx];
    __syncthreads();
#pragma unroll
    for (int i = 0; i < 32; i += 8)
        X[((size_t)(b * SP + s0 + ty + i)) * CDIM + c0 + tx] = tile[tx][ty + i];
}

/* ------- LayerNorm 768 -> int8 two-digit rows [a0 | a1] + per-row scale ------- */
__global__ void ln_packq_kernel(const float* __restrict__ in, const float* __restrict__ gamma,
                                const float* __restrict__ beta, int8_t* __restrict__ dst,
                                float* __restrict__ sA, const int* __restrict__ map) {
    __shared__ float red[32];
    int t = blockIdx.x;
    int src = map ? map[t] : t;
    const float* row = in + (size_t)src * CDIM;
    int8_t* orow = dst + (size_t)t * 1536;
    int tid = threadIdx.x;
    float v0 = row[tid], v1 = row[tid + 256], v2 = row[tid + 512];
    float mu = blk_sum(v0 + v1 + v2, red, tid) * (1.0f / CDIM);
    float d0 = v0 - mu, d1 = v1 - mu, d2 = v2 - mu;
    float var = blk_sum(d0 * d0 + d1 * d1 + d2 * d2, red, tid) * (1.0f / CDIM);
    float inv = rsqrtf(var + 1e-5f);
    float y0 = d0 * inv * gamma[tid] + beta[tid];
    float y1 = d1 * inv * gamma[tid + 256] + beta[tid + 256];
    float y2 = d2 * inv * gamma[tid + 512] + beta[tid + 512];
    float am = blk_max(fmaxf(fabsf(y0), fmaxf(fabsf(y1), fabsf(y2))), red, tid);
    float qs = (am > 0.f) ? 127.f / am : 0.f;
    if (tid == 0) sA[t] = (am > 0.f) ? am / 127.f : 1.f;
    quant2(y0 * qs, orow + tid,       orow + 768 + tid);
    quant2(y1 * qs, orow + tid + 256, orow + 768 + tid + 256);
    quant2(y2 * qs, orow + tid + 512, orow + 768 + tid + 512);
}

/* ------- generic row quantizer: fp32 [*, K] -> int8 [a0|a1], per-row scale ------- */
__global__ void packq_kernel(const float* __restrict__ src, int8_t* __restrict__ dst,
                             float* __restrict__ sA, int K) {
    __shared__ float red[32];
    int t = blockIdx.x;
    int tid = threadIdx.x;
    const float* row = src + (size_t)t * K;
    int8_t* orow = dst + (size_t)t * 2 * K;
    int E = K >> 8;
    float am = 0.f;
    for (int e = 0; e < E; e++) am = fmaxf(am, fabsf(row[tid + e * 256]));
    am = blk_max(am, red, tid);
    float qs = (am > 0.f) ? 127.f / am : 0.f;
    if (tid == 0) sA[t] = (am > 0.f) ? am / 127.f : 1.f;
    for (int e = 0; e < E; e++) {
        int c = tid + e * 256;
        quant2(row[c] * qs, orow + c, orow + K + c);
    }
}

/* ------- weight quantizer: one block per row n ------- */
__global__ void pack_wq_kernel(const float* __restrict__ src, int8_t* __restrict__ dst,
                               float* __restrict__ sW, int Nreal, int Npad, int K,
                               size_t srcStride, size_t dstStride) {
    __shared__ float red[32];
    int z = blockIdx.z;
    int n = blockIdx.x;
    src += (size_t)z * srcStride;
    dst += (size_t)z * dstStride;
    sW += (size_t)z * Npad;
    int tid = threadIdx.x;
    int E = K >> 8;
    int8_t* orow = dst + (size_t)n * 2 * K;
    if (n >= Nreal) {
        for (int e = 0; e < E; e++) {
            int c = tid + e * 256;
            orow[c] = 0; orow[K + c] = 0;
        }
        if (tid == 0) sW[n] = 1.f;
        return;
    }
    const float* row = src + (size_t)n * K;
    float am = 0.f;
    for (int e = 0; e < E; e++) am = fmaxf(am, fabsf(row[tid + e * 256]));
    am = blk_max(am, red, tid);
    float qs = (am > 0.f) ? 127.f / am : 0.f;
    if (tid == 0) sW[n] = (am > 0.f) ? am / 127.f : 1.f;
    for (int e = 0; e < E; e++) {
        int c = tid + e * 256;
        quant2(row[c] * qs, orow + c, orow + K + c);
    }
}

/* ---------------- int8 mma.sync GEMM: two-digit split, H / L passes ----------------
   A: [M][2K] int8 = [a0|a1], B: [Npad][2K] = [w0|w1]. k-tile = 128 int8 = 128B rows.
   PASS 0 (H): acc = a0.w0, write fp32 Hbuf[m*N+col].
   PASS 1 (L): acc = a0.w1 + a1.w0; out = act(sA*sW*(H + acc/128) + bias) (+Res, mapC). */
#define GSMEM (3 * 32768)
template<int ACT, int PASS>
__global__ void __launch_bounds__(256) gemm_q(
    const int8_t* __restrict__ A, const int8_t* __restrict__ B,
    const float* __restrict__ bias, float* __restrict__ Out,
    const float* __restrict__ Res, const int* __restrict__ mapC,
    float* __restrict__ Hbuf, const float* __restrict__ sA, const float* __restrict__ sW,
    int Nreal, int K) {
    extern __shared__ char smraw[];
    uint32_t sbase = smem_u32(smraw);
    const int tid = threadIdx.x;
    const int nt = blockIdx.x, mt = blockIdx.y;
    const int KI = K >> 7;                 /* 128 int8 per k-tile */
    const int KT = (PASS == 0) ? KI : 2 * KI;
    const int K2 = 2 * K;

    const int lr0 = tid >> 3;
    const int lkg = tid & 7;
    const uint32_t lswz = (uint32_t)((lkg ^ (lr0 & 7)) * 16);
    const int8_t* Ag = A + (size_t)(mt * 128 + lr0) * K2 + lkg * 16;
    const int8_t* Bg = B + (size_t)(nt * 128 + lr0) * K2 + lkg * 16;
    uint32_t soffs[4];
#pragma unroll
    for (int i = 0; i < 4; i++) soffs[i] = (uint32_t)((lr0 + 32 * i) * 128) + lswz;

    const int lane = tid & 31, wid = tid >> 5;
    const int wm = wid & 1, wn = wid >> 1;
    const int arow = wm * 64 + (lane & 15);
    const int khalfA = lane >> 4;
    const int ar7 = arow & 7;
    uint32_t aoffs[4];
#pragma unroll
    for (int i = 0; i < 4; i++) aoffs[i] = (uint32_t)((arow + 16 * i) * 128);
    const int brow = wn * 32 + (lane & 7) + ((lane >> 4) << 3);
    const int kaddB = (lane >> 3) & 1;
    const int br7 = brow & 7;
    uint32_t boffs[2];
#pragma unroll
    for (int p = 0; p < 2; p++) boffs[p] = (uint32_t)(16384 + (brow + 16 * p) * 128);

    int acc[4][4][4];
#pragma unroll
    for (int i = 0; i < 4; i++)
#pragma unroll
        for (int j = 0; j < 4; j++)
#pragma unroll
            for (int r = 0; r < 4; r++) acc[i][j][r] = 0;

#pragma unroll
    for (int pl = 0; pl < 2; pl++) {
        int bsl = (PASS == 0) ? pl : pl + KI;
        uint32_t sa = sbase + pl * 32768, sb = sa + 16384;
        const int8_t* ga = Ag + (size_t)pl * 128;
        const int8_t* gb = Bg + (size_t)bsl * 128;
#pragma unroll
        for (int i = 0; i < 4; i++) {
            CP16(sa + soffs[i], ga + (size_t)(32 * i) * K2);
            CP16(sb + soffs[i], gb + (size_t)(32 * i) * K2);
        }
        CP_COMMIT();
    }

    for (int kt = 0; kt < KT; kt++) {
        CP_WAIT1();
        __syncthreads();
        int s = kt - (kt / 3) * 3;
        int nk = kt + 2;
        if (nk < KT) {
            int s2 = nk - (nk / 3) * 3;
            int bsl = (PASS == 0) ? nk : ((nk < KI) ? nk + KI : nk - KI);
            uint32_t sa = sbase + s2 * 32768, sb = sa + 16384;
            const int8_t* ga = Ag + (size_t)nk * 128;
            const int8_t* gb = Bg + (size_t)bsl * 128;
#pragma unroll
            for (int i = 0; i < 4; i++) {
                CP16(sa + soffs[i], ga + (size_t)(32 * i) * K2);
                CP16(sb + soffs[i], gb + (size_t)(32 * i) * K2);
            }
        }
        CP_COMMIT();
        uint32_t st = sbase + s * 32768;
#pragma unroll
        for (int ks = 0; ks < 4; ks++) {
            uint32_t a[4][4], b[2][4];
            uint32_t aswz = (uint32_t)(((2 * ks + khalfA) ^ ar7) * 16);
#pragma unroll
            for (int i = 0; i < 4; i++) LDSM4(a[i], st + aoffs[i] + aswz);
            uint32_t bswz = (uint32_t)(((2 * ks + kaddB) ^ br7) * 16);
#pragma unroll
            for (int p = 0; p < 2; p++) LDSM4(b[p], st + boffs[p] + bswz);
#pragma unroll
            for (int i = 0; i < 4; i++)
#pragma unroll
                for (int j = 0; j < 4; j++)
                    MMAS8(acc[i][j], a[i], b[j >> 1][(j & 1) * 2], b[j >> 1][(j & 1) * 2 + 1]);
        }
    }

    const int g = lane >> 2, tg = lane & 3;
#pragma unroll
    for (int i = 0; i < 4; i++) {
#pragma unroll
        for (int rh = 0; rh < 2; rh++) {
            int m = mt * 128 + wm * 64 + i * 16 + g + rh * 8;
            if (PASS == 0) {
                float* hp = Hbuf + (size_t)m * Nreal;
#pragma unroll
                for (int j = 0; j < 4; j++) {
                    int col = nt * 128 + wn * 32 + j * 8 + tg * 2;
                    if (col < Nreal) {
                        float2 h2 = make_float2((float)acc[i][j][rh * 2 + 0],
                                                (float)acc[i][j][rh * 2 + 1]);
                        *(float2*)(hp + col) = h2;
                    }
                }
            } else {
                float sa_m = sA[m];
                int orow = mapC ? mapC[m] : m;
                float* op = Out + (size_t)orow * Nreal;
                const float* hp = Hbuf + (size_t)m * Nreal;
                const float* rp = Res ? Res + (size_t)orow * Nreal : nullptr;
#pragma unroll
                for (int j = 0; j < 4; j++) {
                    int col = nt * 128 + wn * 32 + j * 8 + tg * 2;
                    if (col < Nreal) {
                        float2 h2 = *(const float2*)(hp + col);
                        float v0 = sa_m * sW[col]     * (h2.x + (float)acc[i][j][rh * 2 + 0] * 0.0078125f) + bias[col];
                        float v1 = sa_m * sW[col + 1] * (h2.y + (float)acc[i][j][rh * 2 + 1] * 0.0078125f) + bias[col + 1];
                        if (ACT == 1) { v0 = gelu_f(v0); v1 = gelu_f(v1); }
                        if (rp) { v0 += rp[col]; v1 += rp[col + 1]; }
                        float2 o2 = make_float2(v0, v1);
                        *(float2*)(op + col) = o2;
                    }
                }
            }
        }
    }
}

/* ---------------- fused window attention (f32x2 QK, expanded bias, fp32 out) ---------------- */
#define ATTN2_FLOATS (3*NWIN*17*2 + 8*4*NWIN + NWIN)
__global__ void __launch_bounds__(256) attn2_kernel(
    const float* __restrict__ qkv, const float* __restrict__ biasE,
    float* __restrict__ aout, int shifted) {
    extern __shared__ float sm[];
    float2* Qs2 = (float2*)sm;
    float2* Ks2 = Qs2 + NWIN * 17;
    float2* Vs2 = Ks2 + NWIN * 17;
    float* probs = (float*)(Vs2 + NWIN * 17);
    int*   lbl   = (int*)(probs + 8 * 4 * NWIN);
    int head = blockIdx.x, win = blockIdx.y;
    int tid = threadIdx.x;
    const float scale = 0.17677669529663687f;

    for (int idx = tid; idx < NWIN * 16; idx += 256) {
        int n = idx >> 4, d2 = idx & 15;
        size_t base = ((size_t)(win * NWIN + n)) * (3 * CDIM) + head * HD + d2 * 2;
        float2 q = *(const float2*)(qkv + base);
        q.x *= scale; q.y *= scale;
        Qs2[n * 17 + d2] = q;
        Ks2[n * 17 + d2] = *(const float2*)(qkv + base + CDIM);
        Vs2[n * 17 + d2] = *(const float2*)(qkv + base + 2 * CDIM);
    }
    if (shifted) {
        int wr = win & 7, wd = wr >> 2, wh = (wr >> 1) & 1, ww = wr & 1;
        for (int n = tid; n < NWIN; n += 256) {
            int d0 = n / 49, r = n % 49, h0 = r / 7, w0 = r % 7;
            int gd = wd * 8 + d0, gh = wh * 7 + h0, gw = ww * 7 + w0;
            int rd = gd < 8 ? 0 : (gd < 12 ? 1 : 2);
            int rh = gh < 7 ? 0 : (gh < 11 ? 1 : 2);
            int rw = gw < 7 ? 0 : (gw < 11 ? 1 : 2);
            lbl[n] = rd * 9 + rh * 3 + rw;
        }
    }
    __syncthreads();

    int warp = tid >> 5, lane = tid & 31;
    float* pw = probs + warp * 4 * NWIN;
    const int d2l = lane & 15, mh = (lane >> 4) * 196;
    const float* biasH = biasE + (size_t)head * NWIN * NWIN;

    for (int bt = 0; bt < 13; bt++) {
        int n0 = warp * 49 + bt * 4;
        int nmax = warp * 49 + 48;
        int nr[4];
#pragma unroll
        for (int r = 0; r < 4; r++) nr[r] = (n0 + r > nmax) ? nmax : n0 + r;

        unsigned long long acc2[4][13];
#pragma unroll
        for (int r = 0; r < 4; r++)
#pragma unroll
            for (int j = 0; j < 13; j++) acc2[r][j] = 0ull;
#pragma unroll 4
        for (int d2 = 0; d2 < 16; d2++) {
            unsigned long long q[4];
#pragma unroll
            for (int r = 0; r < 4; r++)
                q[r] = *(const unsigned long long*)&Qs2[nr[r] * 17 + d2];
#pragma unroll
            for (int j = 0; j < 12; j++) {
                unsigned long long k2 = *(const unsigned long long*)&Ks2[(j * 32 + lane) * 17 + d2];
#pragma unroll
                for (int r = 0; r < 4; r++)
                    FMA2(acc2[r][j], q[r], k2);
            }
            if (lane < 8) {
                unsigned long long k2 = *(const unsigned long long*)&Ks2[(384 + lane) * 17 + d2];
#pragma unroll
                for (int r = 0; r < 4; r++)
                    FMA2(acc2[r][12], q[r], k2);
            }
        }

        float invs[4];
#pragma unroll
        for (int r = 0; r < 4; r++) {
            const float* brow_ = biasH + (size_t)nr[r] * NWIN;
            int nl = shifted ? lbl[nr[r]] : 0;
            float mx = -1e30f;
            float sv[13];
#pragma unroll
            for (int j = 0; j < 13; j++) {
                int m = j * 32 + lane;
                float s;
                if (m < NWIN) {
                    float2 a2;
                    memcpy(&a2, &acc2[r][j], 8);
                    s = a2.x + a2.y + __ldg(brow_ + m);
                    if (shifted && lbl[m] != nl) s -= 100.f;
                } else s = -3e38f;
                sv[j] = s;
                mx = fmaxf(mx, s);
            }
#pragma unroll
            for (int o = 16; o; o >>= 1) mx = fmaxf(mx, __shfl_xor_sync(0xffffffffu, mx, o));
            float sum = 0.f;
#pragma unroll
            for (int j = 0; j < 13; j++) {
                int m = j * 32 + lane;
                float e = (m < NWIN) ? __expf(sv[j] - mx) : 0.f;
                sum += e;
                if (m < NWIN) pw[m * 4 + r] = e;
            }
#pragma unroll
            for (int o = 16; o; o >>= 1) sum += __shfl_xor_sync(0xffffffffu, sum, o);
            invs[r] = 1.f / sum;
        }
        __syncwarp();

        float2 o[4];
#pragma unroll
        for (int r = 0; r < 4; r++) o[r] = make_float2(0.f, 0.f);
#pragma unroll 4
        for (int m = 0; m < 196; m++) {
            float2 v = Vs2[(m + mh) * 17 + d2l];
            float4 p = *(const float4*)(pw + (m + mh) * 4);
            o[0].x += p.x * v.x; o[0].y += p.x * v.y;
            o[1].x += p.y * v.x; o[1].y += p.y * v.y;
            o[2].x += p.z * v.x; o[2].y += p.z * v.y;
            o[3].x += p.w * v.x; o[3].y += p.w * v.y;
        }
#pragma unroll
        for (int r = 0; r < 4; r++) {
            o[r].x += __shfl_down_sync(0xffffffffu, o[r].x, 16);
            o[r].y += __shfl_down_sync(0xffffffffu, o[r].y, 16);
        }
        if (lane < 16) {
#pragma unroll
            for (int r = 0; r < 4; r++) {
                float2 ov = make_float2(o[r].x * invs[r], o[r].y * invs[r]);
                *(float2*)(aout + (size_t)(win * NWIN + nr[r]) * CDIM + head * HD + d2l * 2) = ov;
            }
        }
        __syncwarp();
    }
}

/* ---------------- conv2 (64 -> 2) + GELU ---------------- */
__global__ void conv2_kernel(const float* __restrict__ T3, const float* __restrict__ w,
                             const float* __restrict__ b, float* __restrict__ O) {
    int t = blockIdx.x * 256 + threadIdx.x;
    if (t >= NT) return;
    const float* r = T3 + (size_t)t * 64;
    float a0 = b[0], a1 = b[1];
#pragma unroll
    for (int k = 0; k < 64; k++) {
        float v = r[k];
        a0 += v * w[k];
        a1 += v * w[64 + k];
    }
    O[t * 2 + 0] = gelu_f(a0);
    O[t * 2 + 1] = gelu_f(a1);
}

__global__ void final_kernel(float* __restrict__ out) {
    int i = blockIdx.x * 256 + threadIdx.x;
    if (i >= NT * 2) return;
    int t = i >> 1, ch = i & 1;
    int b = t / SP, sp = t % SP;
    out[((size_t)(b * 2 + ch)) * SP + sp] = g_O[0][i] * g_O[1][i];
}

/* ---------------- host ---------------- */
extern "C" void kernel_launch(void* const* d_in, const int* in_sizes, int n_in,
                              void* d_out, int out_size) {
    const float* x      = (const float*)d_in[0];
    const float* n1_g   = (const float*)d_in[1];
    const float* n1_b   = (const float*)d_in[2];
    const float* qkv_w  = (const float*)d_in[3];
    const float* qkv_b  = (const float*)d_in[4];
    const float* proj_w = (const float*)d_in[5];
    const float* proj_b = (const float*)d_in[6];
    const float* rpb    = (const float*)d_in[7];
    const float* n2_g   = (const float*)d_in[8];
    const float* n2_b   = (const float*)d_in[9];
    const float* fc1_w  = (const float*)d_in[10];
    const float* fc1_b  = (const float*)d_in[11];
    const float* fc2_w  = (const float*)d_in[12];
    const float* fc2_b  = (const float*)d_in[13];
    const float* hln_g  = (const float*)d_in[14];
    const float* hln_b  = (const float*)d_in[15];
    const float* c1_w   = (const float*)d_in[16];
    const float* c1_b   = (const float*)d_in[17];
    const float* c2_w   = (const float*)d_in[18];
    const float* c2_b   = (const float*)d_in[19];
    const int*   rpi    = (const int*)d_in[20];
    float* out = (float*)d_out;

    float *pXs, *pX, *pQKV, *pAO, *pH, *pT3, *pO, *pBiasE, *psA, *psA2;
    float *psWq, *psWp, *psWf1, *psWf2, *psWc1;
    int* pmap;
    int8_t *pWq, *pWp_, *pWf1, *pWf2, *pWc1, *pAp, *pAp2;
    cudaGetSymbolAddress((void**)&pXs,  g_Xs);
    cudaGetSymbolAddress((void**)&pX,   g_X);
    cudaGetSymbolAddress((void**)&pQKV, g_QKV);
    cudaGetSymbolAddress((void**)&pAO,  g_AO);
    cudaGetSymbolAddress((void**)&pH,   g_H);
    cudaGetSymbolAddress((void**)&pT3,  g_T3);
    cudaGetSymbolAddress((void**)&pO,   g_O);
    cudaGetSymbolAddress((void**)&pBiasE, g_BiasE);
    cudaGetSymbolAddress((void**)&pmap, g_map);
    cudaGetSymbolAddress((void**)&pWq,  g_Wq);
    cudaGetSymbolAddress((void**)&pWp_, g_Wp);
    cudaGetSymbolAddress((void**)&pWf1, g_Wf1);
    cudaGetSymbolAddress((void**)&pWf2, g_Wf2);
    cudaGetSymbolAddress((void**)&pWc1, g_Wc1);
    cudaGetSymbolAddress((void**)&psWq,  g_sWq);
    cudaGetSymbolAddress((void**)&psWp,  g_sWp);
    cudaGetSymbolAddress((void**)&psWf1, g_sWf1);
    cudaGetSymbolAddress((void**)&psWf2, g_sWf2);
    cudaGetSymbolAddress((void**)&psWc1, g_sWc1);
    cudaGetSymbolAddress((void**)&pAp,  g_Ap);
    cudaGetSymbolAddress((void**)&pAp2, g_Ap2);
    cudaGetSymbolAddress((void**)&psA,  g_sA);
    cudaGetSymbolAddress((void**)&psA2, g_sA2);

    static cudaStream_t s1 = nullptr;
    static cudaEvent_t evF = nullptr, evJ = nullptr, evP0 = nullptr, evP1 = nullptr;
    if (!s1) {
        cudaStreamCreateWithFlags(&s1, cudaStreamNonBlocking);
        cudaEventCreateWithFlags(&evF, cudaEventDisableTiming);
        cudaEventCreateWithFlags(&evJ, cudaEventDisableTiming);
        cudaEventCreateWithFlags(&evP0, cudaEventDisableTiming);
        cudaEventCreateWithFlags(&evP1, cudaEventDisableTiming);
    }

    const int attn_smem = ATTN2_FLOATS * 4;
    cudaFuncSetAttribute(attn2_kernel, cudaFuncAttributeMaxDynamicSharedMemorySize, attn_smem);
    cudaFuncSetAttribute(gemm_q<0,0>, cudaFuncAttributeMaxDynamicSharedMemorySize, GSMEM);
    cudaFuncSetAttribute(gemm_q<0,1>, cudaFuncAttributeMaxDynamicSharedMemorySize, GSMEM);
    cudaFuncSetAttribute(gemm_q<1,1>, cudaFuncAttributeMaxDynamicSharedMemorySize, GSMEM);

    cudaEventRecord(evF, 0);
    cudaStreamWaitEvent(s1, evF, 0);

    const int biasE_grid = (int)(((size_t)HEADS * NWIN * NWIN + 255) / 256);
    const size_t BE_SZ = (size_t)HEADS * NWIN * NWIN;

    /* setup: pack weights + transpose + bias tables, split across streams */
    init_maps_kernel<<<(NT + 255) / 256, 256>>>();
    transpose_in_kernel<<<dim3(SP / 32, CDIM / 32, B_), dim3(32, 8)>>>(x, pXs);
    pack_wq_kernel<<<dim3(2304, 1, 4), 256>>>(qkv_w, pWq, psWq, 2304, 2304, 768,
                                              (size_t)2304 * 768, (size_t)EW_QKV);
    pack_wq_kernel<<<dim3(768, 1, 4), 256>>>(proj_w, pWp_, psWp, 768, 768, 768,
                                             (size_t)768 * 768, (size_t)EW_PROJ);
    pack_wq_kernel<<<dim3(128, 1, 2), 256>>>(c1_w, pWc1, psWc1, 64, 128, 768,
                                             (size_t)64 * 768, (size_t)EW_C1);
    bias_exp_kernel<<<biasE_grid, 256>>>(rpb + 0 * RPB_SZ * HEADS, rpi, pBiasE + 0 * BE_SZ);
    bias_exp_kernel<<<biasE_grid, 256>>>(rpb + 1 * RPB_SZ * HEADS, rpi, pBiasE + 1 * BE_SZ);
    cudaEventRecord(evP0, 0);
    pack_wq_kernel<<<dim3(3072, 1, 4), 256, 0, s1>>>(fc1_w, pWf1, psWf1, 3072, 3072, 768,
                                                     (size_t)3072 * 768, (size_t)EW_FC1);
    pack_wq_kernel<<<dim3(768, 1, 4), 256, 0, s1>>>(fc2_w, pWf2, psWf2, 768, 768, 3072,
                                                    (size_t)768 * 3072, (size_t)EW_FC2);
    bias_exp_kernel<<<biasE_grid, 256, 0, s1>>>(rpb + 2 * RPB_SZ * HEADS, rpi, pBiasE + 2 * BE_SZ);
    bias_exp_kernel<<<biasE_grid, 256, 0, s1>>>(rpb + 3 * RPB_SZ * HEADS, rpi, pBiasE + 3 * BE_SZ);
    cudaEventRecord(evP1, s1);
    cudaStreamWaitEvent(0, evP1, 0);
    cudaStreamWaitEvent(s1, evP0, 0);

    for (int br = 0; br < 2; br++) {
        cudaStream_t st = br ? s1 : (cudaStream_t)0;
        float* bX   = pX   + (size_t)br * NT * CDIM;
        float* bQKV = pQKV + (size_t)br * NT * 3 * CDIM;
        float* bAO  = pAO  + (size_t)br * NT * CDIM;
        float* bH   = pH   + (size_t)br * NT * 3072;
        float* bT3  = pT3  + (size_t)br * NT * 64;
        float* bsA  = psA  + (size_t)br * NT;
        float* bsA2 = psA2 + (size_t)br * NT;
        int8_t* bAp  = pAp  + (size_t)br * NT * 1536;
        int8_t* bAp2 = pAp2 + (size_t)br * NT * 6144;

        for (int bl = 0; bl < 2; bl++) {
            int s = bl;
            size_t wo = (size_t)(br * 2 + bl);
            const float* inX = (bl == 0) ? pXs : bX;
            float* bBE = pBiasE + wo * BE_SZ;

            ln_packq_kernel<<<NT, 256, 0, st>>>(inX, n1_g + wo * CDIM, n1_b + wo * CDIM,
                                                bAp, bsA, pmap + s * NT);
            gemm_q<0,0><<<dim3(18, 49), 256, GSMEM, st>>>(
                bAp, pWq + wo * EW_QKV, nullptr, nullptr, nullptr, nullptr,
                bH, nullptr, nullptr, 2304, 768);
            gemm_q<0,1><<<dim3(18, 49), 256, GSMEM, st>>>(
                bAp, pWq + wo * EW_QKV, qkv_b + wo * 2304, bQKV, nullptr, nullptr,
                bH, bsA, psWq + wo * 2304, 2304, 768);
            attn2_kernel<<<dim3(HEADS, BW), 256, attn_smem, st>>>(bQKV, bBE, bAO, s);
            packq_kernel<<<NT, 256, 0, st>>>(bAO, bAp, bsA, 768);
            gemm_q<0,0><<<dim3(6, 49), 256, GSMEM, st>>>(
                bAp, pWp_ + wo * EW_PROJ, nullptr, nullptr, nullptr, nullptr,
                bH, nullptr, nullptr, 768, 768);
            gemm_q<0,1><<<dim3(6, 49), 256, GSMEM, st>>>(
                bAp, pWp_ + wo * EW_PROJ, proj_b + wo * CDIM, bX, inX, pmap + s * NT,
                bH, bsA, psWp + wo * 768, 768, 768);
            ln_packq_kernel<<<NT, 256, 0, st>>>(bX, n2_g + wo * CDIM, n2_b + wo * CDIM,
                                                bAp, bsA, nullptr);
            gemm_q<0,0><<<dim3(24, 49), 256, GSMEM, st>>>(
                bAp, pWf1 + wo * EW_FC1, nullptr, nullptr, nullptr, nullptr,
                bH, nullptr, nullptr, 3072, 768);
            gemm_q<1,1><<<dim3(24, 49), 256, GSMEM, st>>>(
                bAp, pWf1 + wo * EW_FC1, fc1_b + wo * 3072, bH, nullptr, nullptr,
                bH, bsA, psWf1 + wo * 3072, 3072, 768);
            packq_kernel<<<NT, 256, 0, st>>>(bH, bAp2, bsA2, 3072);
            gemm_q<0,0><<<dim3(6, 49), 256, GSMEM, st>>>(
                bAp2, pWf2 + wo * EW_FC2, nullptr, nullptr, nullptr, nullptr,
                bH, nullptr, nullptr, 768, 3072);
            gemm_q<0,1><<<dim3(6, 49), 256, GSMEM, st>>>(
                bAp2, pWf2 + wo * EW_FC2, fc2_b + wo * CDIM, bX, bX, nullptr,
                bH, bsA2, psWf2 + wo * 768, 768, 3072);
        }
        ln_packq_kernel<<<NT, 256, 0, st>>>(bX, hln_g + br * CDIM, hln_b + br * CDIM,
                                            bAp, bsA, nullptr);
        gemm_q<0,0><<<dim3(1, 49), 256, GSMEM, st>>>(
            bAp, pWc1 + br * EW_C1, nullptr, nullptr, nullptr, nullptr,
            bH, nullptr, nullptr, 64, 768);
        gemm_q<1,1><<<dim3(1, 49), 256, GSMEM, st>>>(
            bAp, pWc1 + br * EW_C1, c1_b + br * 64, bT3, nullptr, nullptr,
            bH, bsA, psWc1 + (size_t)br * 128, 64, 768);
        conv2_kernel<<<(NT + 255) / 256, 256, 0, st>>>(bT3, c2_w + br * 2 * 64, c2_b + br * 2,
                                                       pO + (size_t)br * NT * 2);
    }

    cudaEventRecord(evJ, s1);
    cudaStreamWaitEvent(0, evJ, 0);
    final_kernel<<<(NT * 2 + 255) / 256, 256>>>(out);
}

// round 13
// speedup vs baseline: 2.1154x; 2.1154x over previous
#include <cuda_runtime.h>
#include <cuda_bf16.h>
#include <math.h>
#include <stdint.h>
#include <string.h>

#define B_    2
#define DD    16
#define HH    14
#define WWQ   14
#define CDIM  768
#define SP    (DD*HH*WWQ)      /* 3136 */
#define NT    (B_*SP)          /* 6272 tokens */
#define NWIN  392
#define BW    16
#define HEADS 24
#define HD    32
#define RPB_SZ 2535

/* packed weight element counts (bf16): [Wh | Wl], row stride 2K */
#define EW_QKV  (2304u*1536u)
#define EW_PROJ (768u*1536u)
#define EW_FC1  (3072u*1536u)
#define EW_FC2  (768u*6144u)
#define EW_C1   (128u*1536u)

/* ---------------- scratch ---------------- */
__device__ float g_Xs [NT*CDIM];                 /* shared transposed input */
__device__ float g_X  [2][NT*CDIM];
__device__ float g_QKV[2][NT*3*CDIM];
__device__ float g_T3 [2][NT*64];
__device__ float g_O  [2][NT*2];
__device__ int   g_map[2][NT];
__device__ float g_BiasE[4][(size_t)HEADS*NWIN*NWIN];   /* per (br,bl) expanded bias */
__device__ __nv_bfloat16 g_Wqkv [4*EW_QKV];
__device__ __nv_bfloat16 g_Wproj[4*EW_PROJ];
__device__ __nv_bfloat16 g_Wfc1 [4*EW_FC1];
__device__ __nv_bfloat16 g_Wfc2 [4*EW_FC2];
__device__ __nv_bfloat16 g_Wc1  [2*EW_C1];
__device__ __nv_bfloat16 g_Ap [2][(size_t)NT*1536];
__device__ __nv_bfloat16 g_Ap2[2][(size_t)NT*6144];

__device__ __forceinline__ float gelu_f(float x) {
    return 0.5f * x * (1.0f + erff(x * 0.70710678118654752f));
}
__device__ __forceinline__ uint32_t smem_u32(const void* p) {
    uint32_t a;
    asm("{ .reg .u64 t; cvta.to.shared.u64 t, %1; cvt.u32.u64 %0, t; }" : "=r"(a) : "l"(p));
    return a;
}
#define CP16(s, g) \
    asm volatile("cp.async.cg.shared.global [%0], [%1], 16;" :: "r"(s), "l"(g) : "memory")
#define CP_COMMIT() asm volatile("cp.async.commit_group;" ::: "memory")
#define CP_WAIT1()  asm volatile("cp.async.wait_group 1;" ::: "memory")
#define LDSM4(r, addr) \
    asm volatile("ldmatrix.sync.aligned.m8n8.x4.shared.b16 {%0,%1,%2,%3}, [%4];" \
        : "=r"((r)[0]), "=r"((r)[1]), "=r"((r)[2]), "=r"((r)[3]) : "r"(addr))
#define MMA16816(c, a, b0, b1) \
    asm volatile("mma.sync.aligned.m16n8k16.row.col.f32.bf16.bf16.f32 " \
        "{%0,%1,%2,%3}, {%4,%5,%6,%7}, {%8,%9}, {%0,%1,%2,%3};" \
        : "+f"((c)[0]), "+f"((c)[1]), "+f"((c)[2]), "+f"((c)[3]) \
        : "r"((a)[0]), "r"((a)[1]), "r"((a)[2]), "r"((a)[3]), "r"(b0), "r"(b1))
/* packed dual fp32 FMA: d = a*b + d (elementwise on 2 lanes) */
#define FMA2(d, a, b) \
    asm("fma.rn.f32x2 %0, %1, %2, %0;" : "+l"(d) : "l"(a), "l"(b))
#define DUP2(d, f) \
    asm("mov.b64 %0, {%1, %1};" : "=l"(d) : "f"(f))
#define UNPK2(lo, hi, v) \
    asm("mov.b64 {%0, %1}, %2;" : "=f"(lo), "=f"(hi) : "l"(v))

/* ---------------- window/roll index maps ---------------- */
__global__ void init_maps_kernel() {
    int wt = blockIdx.x * blockDim.x + threadIdx.x;
    if (wt >= NT) return;
    int win = wt / NWIN, n = wt % NWIN;
    int b = win >> 3, wr = win & 7;
    int wd = wr >> 2, wh = (wr >> 1) & 1, ww = wr & 1;
    int d0 = n / 49, r = n % 49, h0 = r / 7, w0 = r % 7;
    for (int s = 0; s < 2; s++) {
        int sd = s ? 4 : 0, sh = s ? 3 : 0, sw = s ? 3 : 0;
        int gd = (wd * 8 + d0 + sd) & 15;
        int gh = (wh * 7 + h0 + sh) % 14;
        int gw = (ww * 7 + w0 + sw) % 14;
        g_map[s][wt] = ((b * DD + gd) * HH + gh) * WWQ + gw;
    }
}

/* ---------------- expand rel-pos bias: biasE[h][n][m] = rpb[rpi[n][m]][h] ---------------- */
__global__ void bias_exp_kernel(const float* __restrict__ rpb, const int* __restrict__ rpi,
                                float* __restrict__ dst) {
    size_t idx = (size_t)blockIdx.x * 256 + threadIdx.x;
    if (idx >= (size_t)HEADS * NWIN * NWIN) return;
    int m = (int)(idx % NWIN);
    int rest = (int)(idx / NWIN);
    int n = rest % NWIN, h = rest / NWIN;
    dst[idx] = rpb[(size_t)rpi[n * NWIN + m] * HEADS + h];
}

/* ---------------- (B,C,D,H,W) -> (token, C) transpose ---------------- */
__global__ void transpose_in_kernel(const float* __restrict__ x, float* __restrict__ X) {
    __shared__ float tile[32][33];
    int b = blockIdx.z;
    int s0 = blockIdx.x * 32, c0 = blockIdx.y * 32;
    int tx = threadIdx.x, ty = threadIdx.y;
#pragma unroll
    for (int i = 0; i < 32; i += 8)
        tile[ty + i][tx] = x[((size_t)(b * CDIM + c0 + ty + i)) * SP + s0 + tx];
    __syncthreads();
#pragma unroll
    for (int i = 0; i < 32; i += 8)
        X[((size_t)(b * SP + s0 + ty + i)) * CDIM + c0 + tx] = tile[tx][ty + i];
}

/* ---------------- LayerNorm over C=768 -> packed bf16 [h | l], row stride 1536 ---------------- */
__global__ void ln_pack_kernel(const float* __restrict__ in, const float* __restrict__ gamma,
                               const float* __restrict__ beta, __nv_bfloat16* __restrict__ dst,
                               const int* __restrict__ map) {
    int t = blockIdx.x;
    int src = map ? map[t] : t;
    const float* row = in + (size_t)src * CDIM;
    __nv_bfloat16* orow = dst + (size_t)t * 1536;
    int tid = threadIdx.x;
    float v0 = row[tid], v1 = row[tid + 256], v2 = row[tid + 512];
    float s = v0 + v1 + v2;
    __shared__ float red[32];
#pragma unroll
    for (int o = 16; o; o >>= 1) s += __shfl_xor_sync(0xffffffffu, s, o);
    if ((tid & 31) == 0) red[tid >> 5] = s;
    __syncthreads();
    if (tid < 32) {
        float t2 = (tid < 8) ? red[tid] : 0.f;
#pragma unroll
        for (int o = 4; o; o >>= 1) t2 += __shfl_xor_sync(0xffffffffu, t2, o);
        if (tid == 0) red[0] = t2;
    }
    __syncthreads();
    float mu = red[0] * (1.0f / CDIM);
    float d0 = v0 - mu, d1 = v1 - mu, d2 = v2 - mu;
    float vs = d0 * d0 + d1 * d1 + d2 * d2;
#pragma unroll
    for (int o = 16; o; o >>= 1) vs += __shfl_xor_sync(0xffffffffu, vs, o);
    __syncthreads();
    if ((tid & 31) == 0) red[tid >> 5] = vs;
    __syncthreads();
    if (tid < 32) {
        float t2 = (tid < 8) ? red[tid] : 0.f;
#pragma unroll
        for (int o = 4; o; o >>= 1) t2 += __shfl_xor_sync(0xffffffffu, t2, o);
        if (tid == 0) red[0] = t2;
    }
    __syncthreads();
    float inv = rsqrtf(red[0] * (1.0f / CDIM) + 1e-5f);
#pragma unroll
    for (int q = 0; q < 3; q++) {
        int c = tid + q * 256;
        float dv = (q == 0 ? d0 : q == 1 ? d1 : d2);
        float v = dv * inv * gamma[c] + beta[c];
        __nv_bfloat16 h = __float2bfloat16(v);
        __nv_bfloat16 l = __float2bfloat16(v - __bfloat162float(h));
        orow[c] = h;
        orow[768 + c] = l;
    }
}

/* ------- pack weights: fp32 [Nreal][K] -> bf16 [Npad][2K] = [Wh | Wl] ------- */
__global__ void pack_w_kernel(const float* __restrict__ src, __nv_bfloat16* __restrict__ dst,
                              int Nreal, int Npad, int K, size_t srcStride, size_t dstStride) {
    int z = blockIdx.z;
    src += (size_t)z * srcStride;
    dst += (size_t)z * dstStride;
    int idx = blockIdx.x * 256 + threadIdx.x;
    if (idx >= Npad * K) return;
    int k = idx % K, n = idx / K;
    float v = (n < Nreal) ? src[(size_t)n * K + k] : 0.f;
    __nv_bfloat16 h = __float2bfloat16(v);
    __nv_bfloat16 l = __float2bfloat16(v - __bfloat162float(h));
    size_t ro = (size_t)n * 2 * K;
    dst[ro + k] = h;
    dst[ro + K + k] = l;
}

/* ---------------- bf16 mma.sync GEMM (8 warps, 64x32 warp tile, 3-stage, 2 CTA/SM) ---------------- */
#define GSMEM (3 * 32768)
template<int ACT, int PACK>
__global__ void __launch_bounds__(256) gemm_mma(
    const __nv_bfloat16* __restrict__ A, const __nv_bfloat16* __restrict__ B,
    const float* __restrict__ bias, float* __restrict__ Out,
    const float* __restrict__ Res, const int* __restrict__ mapC,
    int Nreal, int K) {
    extern __shared__ char smraw[];
    uint32_t sbase = smem_u32(smraw);
    const int tid = threadIdx.x;
    const int nt = blockIdx.x, mt = blockIdx.y;
    const int KI3 = K >> 6;
    const int KT = 3 * KI3;
    const int K2 = 2 * K;

    const int lr0 = tid >> 3;
    const int lkg = tid & 7;
    const uint32_t lswz = (uint32_t)((lkg ^ (lr0 & 7)) * 16);
    const __nv_bfloat16* Ag = A + (size_t)(mt * 128 + lr0) * K2 + lkg * 8;
    const __nv_bfloat16* Bg = B + (size_t)(nt * 128 + lr0) * K2 + lkg * 8;
    uint32_t soffs[4];
#pragma unroll
    for (int i = 0; i < 4; i++) soffs[i] = (uint32_t)((lr0 + 32 * i) * 128) + lswz;

    const int lane = tid & 31, wid = tid >> 5;
    const int wm = wid & 1, wn = wid >> 1;
    const int arow = wm * 64 + (lane & 15);
    const int khalfA = lane >> 4;
    const int ar7 = arow & 7;
    uint32_t aoffs[4];
#pragma unroll
    for (int i = 0; i < 4; i++) aoffs[i] = (uint32_t)((arow + 16 * i) * 128);
    const int brow = wn * 32 + (lane & 7) + ((lane >> 4) << 3);
    const int kaddB = (lane >> 3) & 1;
    const int br7 = brow & 7;
    uint32_t boffs[2];
#pragma unroll
    for (int p = 0; p < 2; p++) boffs[p] = (uint32_t)(16384 + (brow + 16 * p) * 128);

    float acc[4][4][4];
#pragma unroll
    for (int i = 0; i < 4; i++)
#pragma unroll
        for (int j = 0; j < 4; j++)
#pragma unroll
            for (int r = 0; r < 4; r++) acc[i][j][r] = 0.f;

#pragma unroll
    for (int pl = 0; pl < 2; pl++) {
        uint32_t sa = sbase + pl * 32768, sb = sa + 16384;
        const __nv_bfloat16* ga = Ag + (size_t)pl * 64;
        const __nv_bfloat16* gb = Bg + (size_t)pl * 64;
#pragma unroll
        for (int i = 0; i < 4; i++) {
            CP16(sa + soffs[i], ga + (size_t)(32 * i) * K2);
            CP16(sb + soffs[i], gb + (size_t)(32 * i) * K2);
        }
        CP_COMMIT();
    }

    for (int kt = 0; kt < KT; kt++) {
        CP_WAIT1();
        __syncthreads();
        int s = kt - (kt / 3) * 3;
        int nk = kt + 2;
        if (nk < KT) {
            int s2 = nk - (nk / 3) * 3;
            int asl = (nk < KI3) ? nk : nk - KI3;
            int bsl = (nk < 2 * KI3) ? nk : nk - 2 * KI3;
            uint32_t sa = sbase + s2 * 32768, sb = sa + 16384;
            const __nv_bfloat16* ga = Ag + (size_t)asl * 64;
            const __nv_bfloat16* gb = Bg + (size_t)bsl * 64;
#pragma unroll
            for (int i = 0; i < 4; i++) {
                CP16(sa + soffs[i], ga + (size_t)(32 * i) * K2);
                CP16(sb + soffs[i], gb + (size_t)(32 * i) * K2);
            }
        }
        CP_COMMIT();
        uint32_t st = sbase + s * 32768;
#pragma unroll
        for (int ks = 0; ks < 4; ks++) {
            uint32_t a[4][4], b[2][4];
            uint32_t aswz = (uint32_t)(((2 * ks + khalfA) ^ ar7) * 16);
#pragma unroll
            for (int i = 0; i < 4; i++) LDSM4(a[i], st + aoffs[i] + aswz);
            uint32_t bswz = (uint32_t)(((2 * ks + kaddB) ^ br7) * 16);
#pragma unroll
            for (int p = 0; p < 2; p++) LDSM4(b[p], st + boffs[p] + bswz);
#pragma unroll
            for (int i = 0; i < 4; i++)
#pragma unroll
                for (int j = 0; j < 4; j++)
                    MMA16816(acc[i][j], a[i], b[j >> 1][(j & 1) * 2], b[j >> 1][(j & 1) * 2 + 1]);
        }
    }

    const int g = lane >> 2, tg = lane & 3;
#pragma unroll
    for (int i = 0; i < 4; i++) {
#pragma unroll
        for (int rh = 0; rh < 2; rh++) {
            int m = mt * 128 + wm * 64 + i * 16 + g + rh * 8;
            if (PACK == 0) {
                int orow = mapC ? mapC[m] : m;
                float* op = Out + (size_t)orow * Nreal;
                const float* rp = Res ? Res + (size_t)orow * Nreal : nullptr;
#pragma unroll
                for (int j = 0; j < 4; j++) {
                    int col = nt * 128 + wn * 32 + j * 8 + tg * 2;
                    if (col < Nreal) {
                        float v0 = acc[i][j][rh * 2 + 0] + bias[col];
                        float v1 = acc[i][j][rh * 2 + 1] + bias[col + 1];
                        if (ACT == 1) { v0 = gelu_f(v0); v1 = gelu_f(v1); }
                        if (rp) { v0 += rp[col]; v1 += rp[col + 1]; }
                        float2 o2 = make_float2(v0, v1);
                        *(float2*)(op + col) = o2;
                    }
                }
            } else {
                __nv_bfloat16* op = (__nv_bfloat16*)Out + (size_t)m * 2 * Nreal;
#pragma unroll
                for (int j = 0; j < 4; j++) {
                    int col = nt * 128 + wn * 32 + j * 8 + tg * 2;
                    float v0 = acc[i][j][rh * 2 + 0] + bias[col];
                    float v1 = acc[i][j][rh * 2 + 1] + bias[col + 1];
                    if (ACT == 1) { v0 = gelu_f(v0); v1 = gelu_f(v1); }
                    __nv_bfloat16 h0 = __float2bfloat16(v0);
                    __nv_bfloat16 h1 = __float2bfloat16(v1);
                    __nv_bfloat16 l0 = __float2bfloat16(v0 - __bfloat162float(h0));
                    __nv_bfloat16 l1 = __float2bfloat16(v1 - __bfloat162float(h1));
                    __nv_bfloat162 hh; hh.x = h0; hh.y = h1;
                    __nv_bfloat162 ll; ll.x = l0; ll.y = l1;
                    *(__nv_bfloat162*)(op + col) = hh;
                    *(__nv_bfloat162*)(op + Nreal + col) = ll;
                }
            }
        }
    }
}

/* ---------------- fused window attention v6: f32x2 QK and AV, expanded bias ---------------- */
#define ATTN2_FLOATS (3*NWIN*17*2 + 8*4*NWIN + NWIN)
__global__ void __launch_bounds__(256) attn2_kernel(
    const float* __restrict__ qkv, const float* __restrict__ biasE,
    __nv_bfloat16* __restrict__ aout, int shifted) {
    extern __shared__ float sm[];
    float2* Qs2 = (float2*)sm;
    float2* Ks2 = Qs2 + NWIN * 17;
    float2* Vs2 = Ks2 + NWIN * 17;
    float* probs = (float*)(Vs2 + NWIN * 17);
    int*   lbl   = (int*)(probs + 8 * 4 * NWIN);
    int head = blockIdx.x, win = blockIdx.y;
    int tid = threadIdx.x;
    const float scale = 0.17677669529663687f;

    for (int idx = tid; idx < NWIN * 16; idx += 256) {
        int n = idx >> 4, d2 = idx & 15;
        size_t base = ((size_t)(win * NWIN + n)) * (3 * CDIM) + head * HD + d2 * 2;
        float2 q = *(const float2*)(qkv + base);
        q.x *= scale; q.y *= scale;
        Qs2[n * 17 + d2] = q;
        Ks2[n * 17 + d2] = *(const float2*)(qkv + base + CDIM);
        Vs2[n * 17 + d2] = *(const float2*)(qkv + base + 2 * CDIM);
    }
    if (shifted) {
        int wr = win & 7, wd = wr >> 2, wh = (wr >> 1) & 1, ww = wr & 1;
        for (int n = tid; n < NWIN; n += 256) {
            int d0 = n / 49, r = n % 49, h0 = r / 7, w0 = r % 7;
            int gd = wd * 8 + d0, gh = wh * 7 + h0, gw = ww * 7 + w0;
            int rd = gd < 8 ? 0 : (gd < 12 ? 1 : 2);
            int rh = gh < 7 ? 0 : (gh < 11 ? 1 : 2);
            int rw = gw < 7 ? 0 : (gw < 11 ? 1 : 2);
            lbl[n] = rd * 9 + rh * 3 + rw;
        }
    }
    __syncthreads();

    int warp = tid >> 5, lane = tid & 31;
    float* pw = probs + warp * 4 * NWIN;
    const int d2l = lane & 15, mh = (lane >> 4) * 196;
    const float* biasH = biasE + (size_t)head * NWIN * NWIN;

    for (int bt = 0; bt < 13; bt++) {
        int n0 = warp * 49 + bt * 4;
        int nmax = warp * 49 + 48;
        int nr[4];
#pragma unroll
        for (int r = 0; r < 4; r++) nr[r] = (n0 + r > nmax) ? nmax : n0 + r;

        /* ---- QK with packed dual-fp32 FMA ---- */
        unsigned long long acc2[4][13];
#pragma unroll
        for (int r = 0; r < 4; r++)
#pragma unroll
            for (int j = 0; j < 13; j++) acc2[r][j] = 0ull;
#pragma unroll 4
        for (int d2 = 0; d2 < 16; d2++) {
            unsigned long long q[4];
#pragma unroll
            for (int r = 0; r < 4; r++)
                q[r] = *(const unsigned long long*)&Qs2[nr[r] * 17 + d2];
#pragma unroll
            for (int j = 0; j < 12; j++) {
                unsigned long long k2 = *(const unsigned long long*)&Ks2[(j * 32 + lane) * 17 + d2];
#pragma unroll
                for (int r = 0; r < 4; r++)
                    FMA2(acc2[r][j], q[r], k2);
            }
            if (lane < 8) {
                unsigned long long k2 = *(const unsigned long long*)&Ks2[(384 + lane) * 17 + d2];
#pragma unroll
                for (int r = 0; r < 4; r++)
                    FMA2(acc2[r][12], q[r], k2);
            }
        }

        float invs[4];
#pragma unroll
        for (int r = 0; r < 4; r++) {
            const float* brow_ = biasH + (size_t)nr[r] * NWIN;
            int nl = shifted ? lbl[nr[r]] : 0;
            float mx = -1e30f;
            float sv[13];
#pragma unroll
            for (int j = 0; j < 13; j++) {
                int m = j * 32 + lane;
                float s;
                if (m < NWIN) {
                    float2 a2;
                    memcpy(&a2, &acc2[r][j], 8);
                    s = a2.x + a2.y + __ldg(brow_ + m);
                    if (shifted && lbl[m] != nl) s -= 100.f;
                } else s = -3e38f;
                sv[j] = s;
                mx = fmaxf(mx, s);
            }
#pragma unroll
            for (int o = 16; o; o >>= 1) mx = fmaxf(mx, __shfl_xor_sync(0xffffffffu, mx, o));
            float sum = 0.f;
#pragma unroll
            for (int j = 0; j < 13; j++) {
                int m = j * 32 + lane;
                float e = (m < NWIN) ? __expf(sv[j] - mx) : 0.f;
                sum += e;
                if (m < NWIN) pw[m * 4 + r] = e;
            }
#pragma unroll
            for (int o = 16; o; o >>= 1) sum += __shfl_xor_sync(0xffffffffu, sum, o);
            invs[r] = 1.f / sum;
        }
        __syncwarp();

        /* ---- AV with packed dual-fp32 FMA: accumulators packed across rows ----
           ox01 = (o0.x, o1.x), ox23 = (o2.x, o3.x), oy01, oy23 similarly. */
        unsigned long long ox01 = 0ull, ox23 = 0ull, oy01 = 0ull, oy23 = 0ull;
#pragma unroll 4
        for (int m = 0; m < 196; m++) {
            float2 v = Vs2[(m + mh) * 17 + d2l];
            const unsigned long long* pp = (const unsigned long long*)(pw + (m + mh) * 4);
            unsigned long long p01 = pp[0], p23 = pp[1];
            unsigned long long vx, vy;
            DUP2(vx, v.x);
            DUP2(vy, v.y);
            FMA2(ox01, p01, vx);
            FMA2(ox23, p23, vx);
            FMA2(oy01, p01, vy);
            FMA2(oy23, p23, vy);
        }
        float2 o[4];
        UNPK2(o[0].x, o[1].x, ox01);
        UNPK2(o[2].x, o[3].x, ox23);
        UNPK2(o[0].y, o[1].y, oy01);
        UNPK2(o[2].y, o[3].y, oy23);
#pragma unroll
        for (int r = 0; r < 4; r++) {
            o[r].x += __shfl_down_sync(0xffffffffu, o[r].x, 16);
            o[r].y += __shfl_down_sync(0xffffffffu, o[r].y, 16);
        }
        if (lane < 16) {
#pragma unroll
            for (int r = 0; r < 4; r++) {
                float vx = o[r].x * invs[r];
                float vy = o[r].y * invs[r];
                __nv_bfloat16 hx = __float2bfloat16(vx);
                __nv_bfloat16 hy = __float2bfloat16(vy);
                __nv_bfloat16 lx = __float2bfloat16(vx - __bfloat162float(hx));
                __nv_bfloat16 ly = __float2bfloat16(vy - __bfloat162float(hy));
                __nv_bfloat16* op = aout + (size_t)(win * NWIN + nr[r]) * 1536 + head * HD + d2l * 2;
                __nv_bfloat162 hh; hh.x = hx; hh.y = hy;
                __nv_bfloat162 ll; ll.x = lx; ll.y = ly;
                *(__nv_bfloat162*)op = hh;
                *(__nv_bfloat162*)(op + 768) = ll;
            }
        }
        __syncwarp();
    }
}

/* ---------------- conv2 (64 -> 2) + GELU ---------------- */
__global__ void conv2_kernel(const float* __restrict__ T3, const float* __restrict__ w,
                             const float* __restrict__ b, float* __restrict__ O) {
    int t = blockIdx.x * 256 + threadIdx.x;
    if (t >= NT) return;
    const float* r = T3 + (size_t)t * 64;
    float a0 = b[0], a1 = b[1];
#pragma unroll
    for (int k = 0; k < 64; k++) {
        float v = r[k];
        a0 += v * w[k];
        a1 += v * w[64 + k];
    }
    O[t * 2 + 0] = gelu_f(a0);
    O[t * 2 + 1] = gelu_f(a1);
}

__global__ void final_kernel(float* __restrict__ out) {
    int i = blockIdx.x * 256 + threadIdx.x;
    if (i >= NT * 2) return;
    int t = i >> 1, ch = i & 1;
    int b = t / SP, sp = t % SP;
    out[((size_t)(b * 2 + ch)) * SP + sp] = g_O[0][i] * g_O[1][i];
}

/* ---------------- host ---------------- */
extern "C" void kernel_launch(void* const* d_in, const int* in_sizes, int n_in,
                              void* d_out, int out_size) {
    const float* x      = (const float*)d_in[0];
    const float* n1_g   = (const float*)d_in[1];
    const float* n1_b   = (const float*)d_in[2];
    const float* qkv_w  = (const float*)d_in[3];
    const float* qkv_b  = (const float*)d_in[4];
    const float* proj_w = (const float*)d_in[5];
    const float* proj_b = (const float*)d_in[6];
    const float* rpb    = (const float*)d_in[7];
    const float* n2_g   = (const float*)d_in[8];
    const float* n2_b   = (const float*)d_in[9];
    const float* fc1_w  = (const float*)d_in[10];
    const float* fc1_b  = (const float*)d_in[11];
    const float* fc2_w  = (const float*)d_in[12];
    const float* fc2_b  = (const float*)d_in[13];
    const float* hln_g  = (const float*)d_in[14];
    const float* hln_b  = (const float*)d_in[15];
    const float* c1_w   = (const float*)d_in[16];
    const float* c1_b   = (const float*)d_in[17];
    const float* c2_w   = (const float*)d_in[18];
    const float* c2_b   = (const float*)d_in[19];
    const int*   rpi    = (const int*)d_in[20];
    float* out = (float*)d_out;

    float *pXs, *pX, *pQKV, *pT3, *pO, *pBiasE;
    int* pmap;
    __nv_bfloat16 *pWq, *pWp_, *pWf1, *pWf2, *pWc1, *pAp, *pAp2;
    cudaGetSymbolAddress((void**)&pXs,  g_Xs);
    cudaGetSymbolAddress((void**)&pX,   g_X);
    cudaGetSymbolAddress((void**)&pQKV, g_QKV);
    cudaGetSymbolAddress((void**)&pT3,  g_T3);
    cudaGetSymbolAddress((void**)&pO,   g_O);
    cudaGetSymbolAddress((void**)&pBiasE, g_BiasE);
    cudaGetSymbolAddress((void**)&pmap, g_map);
    cudaGetSymbolAddress((void**)&pWq,  g_Wqkv);
    cudaGetSymbolAddress((void**)&pWp_, g_Wproj);
    cudaGetSymbolAddress((void**)&pWf1, g_Wfc1);
    cudaGetSymbolAddress((void**)&pWf2, g_Wfc2);
    cudaGetSymbolAddress((void**)&pWc1, g_Wc1);
    cudaGetSymbolAddress((void**)&pAp,  g_Ap);
    cudaGetSymbolAddress((void**)&pAp2, g_Ap2);

    static cudaStream_t s1 = nullptr;
    static cudaEvent_t evF = nullptr, evJ = nullptr, evP0 = nullptr, evP1 = nullptr;
    if (!s1) {
        cudaStreamCreateWithFlags(&s1, cudaStreamNonBlocking);
        cudaEventCreateWithFlags(&evF, cudaEventDisableTiming);
        cudaEventCreateWithFlags(&evJ, cudaEventDisableTiming);
        cudaEventCreateWithFlags(&evP0, cudaEventDisableTiming);
        cudaEventCreateWithFlags(&evP1, cudaEventDisableTiming);
    }

    const int attn_smem = ATTN2_FLOATS * 4;
    cudaFuncSetAttribute(attn2_kernel, cudaFuncAttributeMaxDynamicSharedMemorySize, attn_smem);
    cudaFuncSetAttribute(gemm_mma<0,0>, cudaFuncAttributeMaxDynamicSharedMemorySize, GSMEM);
    cudaFuncSetAttribute(gemm_mma<1,0>, cudaFuncAttributeMaxDynamicSharedMemorySize, GSMEM);
    cudaFuncSetAttribute(gemm_mma<1,1>, cudaFuncAttributeMaxDynamicSharedMemorySize, GSMEM);

    cudaEventRecord(evF, 0);
    cudaStreamWaitEvent(s1, evF, 0);

    const int biasE_grid = (int)(((size_t)HEADS * NWIN * NWIN + 255) / 256);
    const size_t BE_SZ = (size_t)HEADS * NWIN * NWIN;

    /* setup phase, split across both streams */
    init_maps_kernel<<<(NT + 255) / 256, 256>>>();
    transpose_in_kernel<<<dim3(SP / 32, CDIM / 32, B_), dim3(32, 8)>>>(x, pXs);
    pack_w_kernel<<<dim3((2304 * 768 + 255) / 256, 1, 4), 256>>>(
        qkv_w, pWq, 2304, 2304, 768, (size_t)2304 * 768, (size_t)EW_QKV);
    pack_w_kernel<<<dim3((768 * 768 + 255) / 256, 1, 4), 256>>>(
        proj_w, pWp_, 768, 768, 768, (size_t)768 * 768, (size_t)EW_PROJ);
    pack_w_kernel<<<dim3((128 * 768 + 255) / 256, 1, 2), 256>>>(
        c1_w, pWc1, 64, 128, 768, (size_t)64 * 768, (size_t)EW_C1);
    bias_exp_kernel<<<biasE_grid, 256>>>(rpb + 0 * RPB_SZ * HEADS, rpi, pBiasE + 0 * BE_SZ);
    bias_exp_kernel<<<biasE_grid, 256>>>(rpb + 1 * RPB_SZ * HEADS, rpi, pBiasE + 1 * BE_SZ);
    cudaEventRecord(evP0, 0);
    pack_w_kernel<<<dim3((3072 * 768 + 255) / 256, 1, 4), 256, 0, s1>>>(
        fc1_w, pWf1, 3072, 3072, 768, (size_t)3072 * 768, (size_t)EW_FC1);
    pack_w_kernel<<<dim3((768 * 3072 + 255) / 256, 1, 4), 256, 0, s1>>>(
        fc2_w, pWf2, 768, 768, 3072, (size_t)768 * 3072, (size_t)EW_FC2);
    bias_exp_kernel<<<biasE_grid, 256, 0, s1>>>(rpb + 2 * RPB_SZ * HEADS, rpi, pBiasE + 2 * BE_SZ);
    bias_exp_kernel<<<biasE_grid, 256, 0, s1>>>(rpb + 3 * RPB_SZ * HEADS, rpi, pBiasE + 3 * BE_SZ);
    cudaEventRecord(evP1, s1);
    cudaStreamWaitEvent(0, evP1, 0);
    cudaStreamWaitEvent(s1, evP0, 0);

    for (int br = 0; br < 2; br++) {
        cudaStream_t st = br ? s1 : (cudaStream_t)0;
        float* bX   = pX   + (size_t)br * NT * CDIM;
        float* bQKV = pQKV + (size_t)br * NT * 3 * CDIM;
        float* bT3  = pT3  + (size_t)br * NT * 64;
        __nv_bfloat16* bAp  = pAp  + (size_t)br * NT * 1536;
        __nv_bfloat16* bAp2 = pAp2 + (size_t)br * NT * 6144;

        for (int bl = 0; bl < 2; bl++) {
            int s = bl;
            size_t wo = (size_t)(br * 2 + bl);
            const float* inX  = (bl == 0) ? pXs : bX;   /* block0 reads shared transpose */
            float* bBE = pBiasE + wo * BE_SZ;
            ln_pack_kernel<<<NT, 256, 0, st>>>(inX, n1_g + wo * CDIM, n1_b + wo * CDIM, bAp, pmap + s * NT);
            gemm_mma<0,0><<<dim3(18, 49), 256, GSMEM, st>>>(
                bAp, pWq + wo * EW_QKV, qkv_b + wo * 2304, bQKV,
                nullptr, nullptr, 2304, 768);
            attn2_kernel<<<dim3(HEADS, BW), 256, attn_smem, st>>>(
                bQKV, bBE, bAp, s);
            gemm_mma<0,0><<<dim3(6, 49), 256, GSMEM, st>>>(
                bAp, pWp_ + wo * EW_PROJ, proj_b + wo * CDIM, bX,
                inX, pmap + s * NT, 768, 768);
            ln_pack_kernel<<<NT, 256, 0, st>>>(bX, n2_g + wo * CDIM, n2_b + wo * CDIM, bAp, nullptr);
            gemm_mma<1,1><<<dim3(24, 49), 256, GSMEM, st>>>(
                bAp, pWf1 + wo * EW_FC1, fc1_b + wo * 3072, (float*)bAp2,
                nullptr, nullptr, 3072, 768);
            gemm_mma<0,0><<<dim3(6, 49), 256, GSMEM, st>>>(
                bAp2, pWf2 + wo * EW_FC2, fc2_b + wo * CDIM, bX,
                bX, nullptr, 768, 3072);
        }
        ln_pack_kernel<<<NT, 256, 0, st>>>(bX, hln_g + br * CDIM, hln_b + br * CDIM, bAp, nullptr);
        gemm_mma<1,0><<<dim3(1, 49), 256, GSMEM, st>>>(
            bAp, pWc1 + br * EW_C1, c1_b + br * 64, bT3,
            nullptr, nullptr, 64, 768);
        conv2_kernel<<<(NT + 255) / 256, 256, 0, st>>>(bT3, c2_w + br * 2 * 64, c2_b + br * 2,
                                                       pO + (size_t)br * NT * 2);
    }

    cudaEventRecord(evJ, s1);
    cudaStreamWaitEvent(0, evJ, 0);
    final_kernel<<<(NT * 2 + 255) / 256, 256>>>(out);
}

// round 14
// speedup vs baseline: 2.1181x; 1.0012x over previous
#include <cuda_runtime.h>
#include <cuda_bf16.h>
#include <math.h>
#include <stdint.h>
#include <string.h>

#define B_    2
#define DD    16
#define HH    14
#define WWQ   14
#define CDIM  768
#define SP    (DD*HH*WWQ)      /* 3136 */
#define NT    (B_*SP)          /* 6272 tokens */
#define NWIN  392
#define BW    16
#define HEADS 24
#define HD    32
#define RPB_SZ 2535

/* packed weight element counts (bf16): [Wh | Wl], row stride 2K */
#define EW_QKV  (2304u*1536u)
#define EW_PROJ (768u*1536u)
#define EW_FC1  (3072u*1536u)
#define EW_FC2  (768u*6144u)
#define EW_C1   (128u*1536u)

/* ---------------- scratch ---------------- */
__device__ float g_Xs [NT*CDIM];                 /* shared transposed input */
__device__ float g_X  [2][NT*CDIM];
__device__ float g_QKV[2][NT*3*CDIM];
__device__ float g_T3 [2][NT*64];
__device__ float g_O  [2][NT*2];
__device__ int   g_map[2][NT];
__device__ float g_BiasE[4][(size_t)HEADS*NWIN*NWIN];   /* per (br,bl) expanded bias */
__device__ __nv_bfloat16 g_Wqkv [4*EW_QKV];
__device__ __nv_bfloat16 g_Wproj[4*EW_PROJ];
__device__ __nv_bfloat16 g_Wfc1 [4*EW_FC1];
__device__ __nv_bfloat16 g_Wfc2 [4*EW_FC2];
__device__ __nv_bfloat16 g_Wc1  [2*EW_C1];
__device__ __nv_bfloat16 g_Ap [2][(size_t)NT*1536];
__device__ __nv_bfloat16 g_Ap2[2][(size_t)NT*6144];

__device__ __forceinline__ float gelu_f(float x) {
    return 0.5f * x * (1.0f + erff(x * 0.70710678118654752f));
}
__device__ __forceinline__ uint32_t smem_u32(const void* p) {
    uint32_t a;
    asm("{ .reg .u64 t; cvta.to.shared.u64 t, %1; cvt.u32.u64 %0, t; }" : "=r"(a) : "l"(p));
    return a;
}
#define CP16(s, g) \
    asm volatile("cp.async.cg.shared.global [%0], [%1], 16;" :: "r"(s), "l"(g) : "memory")
#define CP_COMMIT() asm volatile("cp.async.commit_group;" ::: "memory")
#define CP_WAIT1()  asm volatile("cp.async.wait_group 1;" ::: "memory")
#define LDSM4(r, addr) \
    asm volatile("ldmatrix.sync.aligned.m8n8.x4.shared.b16 {%0,%1,%2,%3}, [%4];" \
        : "=r"((r)[0]), "=r"((r)[1]), "=r"((r)[2]), "=r"((r)[3]) : "r"(addr))
#define MMA16816(c, a, b0, b1) \
    asm volatile("mma.sync.aligned.m16n8k16.row.col.f32.bf16.bf16.f32 " \
        "{%0,%1,%2,%3}, {%4,%5,%6,%7}, {%8,%9}, {%0,%1,%2,%3};" \
        : "+f"((c)[0]), "+f"((c)[1]), "+f"((c)[2]), "+f"((c)[3]) \
        : "r"((a)[0]), "r"((a)[1]), "r"((a)[2]), "r"((a)[3]), "r"(b0), "r"(b1))
/* packed dual fp32 FMA: d = a*b + d (elementwise on 2 lanes) */
#define FMA2(d, a, b) \
    asm("fma.rn.f32x2 %0, %1, %2, %0;" : "+l"(d) : "l"(a), "l"(b))
#define DUP2(d, f) \
    asm("mov.b64 %0, {%1, %1};" : "=l"(d) : "f"(f))
#define UNPK2(lo, hi, v) \
    asm("mov.b64 {%0, %1}, %2;" : "=f"(lo), "=f"(hi) : "l"(v))

/* ---------------- window/roll index maps ---------------- */
__global__ void init_maps_kernel() {
    int wt = blockIdx.x * blockDim.x + threadIdx.x;
    if (wt >= NT) return;
    int win = wt / NWIN, n = wt % NWIN;
    int b = win >> 3, wr = win & 7;
    int wd = wr >> 2, wh = (wr >> 1) & 1, ww = wr & 1;
    int d0 = n / 49, r = n % 49, h0 = r / 7, w0 = r % 7;
    for (int s = 0; s < 2; s++) {
        int sd = s ? 4 : 0, sh = s ? 3 : 0, sw = s ? 3 : 0;
        int gd = (wd * 8 + d0 + sd) & 15;
        int gh = (wh * 7 + h0 + sh) % 14;
        int gw = (ww * 7 + w0 + sw) % 14;
        g_map[s][wt] = ((b * DD + gd) * HH + gh) * WWQ + gw;
    }
}

/* ---------------- expand rel-pos bias: biasE[h][n][m] = rpb[rpi[n][m]][h] ---------------- */
__global__ void bias_exp_kernel(const float* __restrict__ rpb, const int* __restrict__ rpi,
                                float* __restrict__ dst) {
    size_t idx = (size_t)blockIdx.x * 256 + threadIdx.x;
    if (idx >= (size_t)HEADS * NWIN * NWIN) return;
    int m = (int)(idx % NWIN);
    int rest = (int)(idx / NWIN);
    int n = rest % NWIN, h = rest / NWIN;
    dst[idx] = rpb[(size_t)rpi[n * NWIN + m] * HEADS + h];
}

/* ---------------- (B,C,D,H,W) -> (token, C) transpose ---------------- */
__global__ void transpose_in_kernel(const float* __restrict__ x, float* __restrict__ X) {
    __shared__ float tile[32][33];
    int b = blockIdx.z;
    int s0 = blockIdx.x * 32, c0 = blockIdx.y * 32;
    int tx = threadIdx.x, ty = threadIdx.y;
#pragma unroll
    for (int i = 0; i < 32; i += 8)
        tile[ty + i][tx] = x[((size_t)(b * CDIM + c0 + ty + i)) * SP + s0 + tx];
    __syncthreads();
#pragma unroll
    for (int i = 0; i < 32; i += 8)
        X[((size_t)(b * SP + s0 + ty + i)) * CDIM + c0 + tx] = tile[tx][ty + i];
}

/* ------- LayerNorm over C=768 -> packed bf16 [h | l], single-pass reduction ------- */
__global__ void ln_pack_kernel(const float* __restrict__ in, const float* __restrict__ gamma,
                               const float* __restrict__ beta, __nv_bfloat16* __restrict__ dst,
                               const int* __restrict__ map) {
    int t = blockIdx.x;
    int src = map ? map[t] : t;
    const float* row = in + (size_t)src * CDIM;
    __nv_bfloat16* orow = dst + (size_t)t * 1536;
    int tid = threadIdx.x;
    float v0 = row[tid], v1 = row[tid + 256], v2 = row[tid + 512];
    float s  = v0 + v1 + v2;
    float sq = v0 * v0 + v1 * v1 + v2 * v2;
    __shared__ float red[16];
#pragma unroll
    for (int o = 16; o; o >>= 1) {
        s  += __shfl_xor_sync(0xffffffffu, s, o);
        sq += __shfl_xor_sync(0xffffffffu, sq, o);
    }
    if ((tid & 31) == 0) { red[tid >> 5] = s; red[8 + (tid >> 5)] = sq; }
    __syncthreads();
    if (tid < 32) {
        float a = (tid < 8) ? red[tid] : 0.f;
        float b = (tid < 8) ? red[8 + tid] : 0.f;
#pragma unroll
        for (int o = 4; o; o >>= 1) {
            a += __shfl_xor_sync(0xffffffffu, a, o);
            b += __shfl_xor_sync(0xffffffffu, b, o);
        }
        if (tid == 0) { red[0] = a; red[8] = b; }
    }
    __syncthreads();
    float mu  = red[0] * (1.0f / CDIM);
    float var = red[8] * (1.0f / CDIM) - mu * mu;
    float inv = rsqrtf(var + 1e-5f);
#pragma unroll
    for (int q = 0; q < 3; q++) {
        int c = tid + q * 256;
        float vv = (q == 0 ? v0 : q == 1 ? v1 : v2);
        float v = (vv - mu) * inv * gamma[c] + beta[c];
        __nv_bfloat16 h = __float2bfloat16(v);
        __nv_bfloat16 l = __float2bfloat16(v - __bfloat162float(h));
        orow[c] = h;
        orow[768 + c] = l;
    }
}

/* ------- pack weights: fp32 [Nreal][K] -> bf16 [Npad][2K] = [Wh | Wl] ------- */
__global__ void pack_w_kernel(const float* __restrict__ src, __nv_bfloat16* __restrict__ dst,
                              int Nreal, int Npad, int K, size_t srcStride, size_t dstStride) {
    int z = blockIdx.z;
    src += (size_t)z * srcStride;
    dst += (size_t)z * dstStride;
    int idx = blockIdx.x * 256 + threadIdx.x;
    if (idx >= Npad * K) return;
    int k = idx % K, n = idx / K;
    float v = (n < Nreal) ? src[(size_t)n * K + k] : 0.f;
    __nv_bfloat16 h = __float2bfloat16(v);
    __nv_bfloat16 l = __float2bfloat16(v - __bfloat162float(h));
    size_t ro = (size_t)n * 2 * K;
    dst[ro + k] = h;
    dst[ro + K + k] = l;
}

/* ---------------- bf16 mma.sync GEMM (8 warps, 64x32 warp tile, 3-stage, 2 CTA/SM) ---------------- */
#define GSMEM (3 * 32768)
template<int ACT, int PACK>
__global__ void __launch_bounds__(256) gemm_mma(
    const __nv_bfloat16* __restrict__ A, const __nv_bfloat16* __restrict__ B,
    const float* __restrict__ bias, float* __restrict__ Out,
    const float* __restrict__ Res, const int* __restrict__ mapC,
    int Nreal, int K) {
    extern __shared__ char smraw[];
    uint32_t sbase = smem_u32(smraw);
    const int tid = threadIdx.x;
    const int nt = blockIdx.x, mt = blockIdx.y;
    const int KI3 = K >> 6;
    const int KT = 3 * KI3;
    const int K2 = 2 * K;

    const int lr0 = tid >> 3;
    const int lkg = tid & 7;
    const uint32_t lswz = (uint32_t)((lkg ^ (lr0 & 7)) * 16);
    const __nv_bfloat16* Ag = A + (size_t)(mt * 128 + lr0) * K2 + lkg * 8;
    const __nv_bfloat16* Bg = B + (size_t)(nt * 128 + lr0) * K2 + lkg * 8;
    uint32_t soffs[4];
#pragma unroll
    for (int i = 0; i < 4; i++) soffs[i] = (uint32_t)((lr0 + 32 * i) * 128) + lswz;

    const int lane = tid & 31, wid = tid >> 5;
    const int wm = wid & 1, wn = wid >> 1;
    const int arow = wm * 64 + (lane & 15);
    const int khalfA = lane >> 4;
    const int ar7 = arow & 7;
    uint32_t aoffs[4];
#pragma unroll
    for (int i = 0; i < 4; i++) aoffs[i] = (uint32_t)((arow + 16 * i) * 128);
    const int brow = wn * 32 + (lane & 7) + ((lane >> 4) << 3);
    const int kaddB = (lane >> 3) & 1;
    const int br7 = brow & 7;
    uint32_t boffs[2];
#pragma unroll
    for (int p = 0; p < 2; p++) boffs[p] = (uint32_t)(16384 + (brow + 16 * p) * 128);

    float acc[4][4][4];
#pragma unroll
    for (int i = 0; i < 4; i++)
#pragma unroll
        for (int j = 0; j < 4; j++)
#pragma unroll
            for (int r = 0; r < 4; r++) acc[i][j][r] = 0.f;

#pragma unroll
    for (int pl = 0; pl < 2; pl++) {
        uint32_t sa = sbase + pl * 32768, sb = sa + 16384;
        const __nv_bfloat16* ga = Ag + (size_t)pl * 64;
        const __nv_bfloat16* gb = Bg + (size_t)pl * 64;
#pragma unroll
        for (int i = 0; i < 4; i++) {
            CP16(sa + soffs[i], ga + (size_t)(32 * i) * K2);
            CP16(sb + soffs[i], gb + (size_t)(32 * i) * K2);
        }
        CP_COMMIT();
    }

    for (int kt = 0; kt < KT; kt++) {
        CP_WAIT1();
        __syncthreads();
        int s = kt - (kt / 3) * 3;
        int nk = kt + 2;
        if (nk < KT) {
            int s2 = nk - (nk / 3) * 3;
            int asl = (nk < KI3) ? nk : nk - KI3;
            int bsl = (nk < 2 * KI3) ? nk : nk - 2 * KI3;
            uint32_t sa = sbase + s2 * 32768, sb = sa + 16384;
            const __nv_bfloat16* ga = Ag + (size_t)asl * 64;
            const __nv_bfloat16* gb = Bg + (size_t)bsl * 64;
#pragma unroll
            for (int i = 0; i < 4; i++) {
                CP16(sa + soffs[i], ga + (size_t)(32 * i) * K2);
                CP16(sb + soffs[i], gb + (size_t)(32 * i) * K2);
            }
        }
        CP_COMMIT();
        uint32_t st = sbase + s * 32768;
#pragma unroll
        for (int ks = 0; ks < 4; ks++) {
            uint32_t a[4][4], b[2][4];
            uint32_t aswz = (uint32_t)(((2 * ks + khalfA) ^ ar7) * 16);
#pragma unroll
            for (int i = 0; i < 4; i++) LDSM4(a[i], st + aoffs[i] + aswz);
            uint32_t bswz = (uint32_t)(((2 * ks + kaddB) ^ br7) * 16);
#pragma unroll
            for (int p = 0; p < 2; p++) LDSM4(b[p], st + boffs[p] + bswz);
#pragma unroll
            for (int i = 0; i < 4; i++)
#pragma unroll
                for (int j = 0; j < 4; j++)
                    MMA16816(acc[i][j], a[i], b[j >> 1][(j & 1) * 2], b[j >> 1][(j & 1) * 2 + 1]);
        }
    }

    const int g = lane >> 2, tg = lane & 3;
#pragma unroll
    for (int i = 0; i < 4; i++) {
#pragma unroll
        for (int rh = 0; rh < 2; rh++) {
            int m = mt * 128 + wm * 64 + i * 16 + g + rh * 8;
            if (PACK == 0) {
                int orow = mapC ? mapC[m] : m;
                float* op = Out + (size_t)orow * Nreal;
                const float* rp = Res ? Res + (size_t)orow * Nreal : nullptr;
#pragma unroll
                for (int j = 0; j < 4; j++) {
                    int col = nt * 128 + wn * 32 + j * 8 + tg * 2;
                    if (col < Nreal) {
                        float v0 = acc[i][j][rh * 2 + 0] + bias[col];
                        float v1 = acc[i][j][rh * 2 + 1] + bias[col + 1];
                        if (ACT == 1) { v0 = gelu_f(v0); v1 = gelu_f(v1); }
                        if (rp) { v0 += rp[col]; v1 += rp[col + 1]; }
                        float2 o2 = make_float2(v0, v1);
                        *(float2*)(op + col) = o2;
                    }
                }
            } else {
                __nv_bfloat16* op = (__nv_bfloat16*)Out + (size_t)m * 2 * Nreal;
#pragma unroll
                for (int j = 0; j < 4; j++) {
                    int col = nt * 128 + wn * 32 + j * 8 + tg * 2;
                    float v0 = acc[i][j][rh * 2 + 0] + bias[col];
                    float v1 = acc[i][j][rh * 2 + 1] + bias[col + 1];
                    if (ACT == 1) { v0 = gelu_f(v0); v1 = gelu_f(v1); }
                    __nv_bfloat16 h0 = __float2bfloat16(v0);
                    __nv_bfloat16 h1 = __float2bfloat16(v1);
                    __nv_bfloat16 l0 = __float2bfloat16(v0 - __bfloat162float(h0));
                    __nv_bfloat16 l1 = __float2bfloat16(v1 - __bfloat162float(h1));
                    __nv_bfloat162 hh; hh.x = h0; hh.y = h1;
                    __nv_bfloat162 ll; ll.x = l0; ll.y = l1;
                    *(__nv_bfloat162*)(op + col) = hh;
                    *(__nv_bfloat162*)(op + Nreal + col) = ll;
                }
            }
        }
    }
}

/* ---------------- fused window attention v7: f32x2 QK/AV, LDS.128 probs ---------------- */
#define ATTN2_FLOATS (3*NWIN*17*2 + 8*4*NWIN + NWIN)
__global__ void __launch_bounds__(256) attn2_kernel(
    const float* __restrict__ qkv, const float* __restrict__ biasE,
    __nv_bfloat16* __restrict__ aout, int shifted) {
    extern __shared__ float sm[];
    float2* Qs2 = (float2*)sm;
    float2* Ks2 = Qs2 + NWIN * 17;
    float2* Vs2 = Ks2 + NWIN * 17;
    float* probs = (float*)(Vs2 + NWIN * 17);
    int*   lbl   = (int*)(probs + 8 * 4 * NWIN);
    int head = blockIdx.x, win = blockIdx.y;
    int tid = threadIdx.x;
    const float scale = 0.17677669529663687f;

    for (int idx = tid; idx < NWIN * 16; idx += 256) {
        int n = idx >> 4, d2 = idx & 15;
        size_t base = ((size_t)(win * NWIN + n)) * (3 * CDIM) + head * HD + d2 * 2;
        float2 q = *(const float2*)(qkv + base);
        q.x *= scale; q.y *= scale;
        Qs2[n * 17 + d2] = q;
        Ks2[n * 17 + d2] = *(const float2*)(qkv + base + CDIM);
        Vs2[n * 17 + d2] = *(const float2*)(qkv + base + 2 * CDIM);
    }
    if (shifted) {
        int wr = win & 7, wd = wr >> 2, wh = (wr >> 1) & 1, ww = wr & 1;
        for (int n = tid; n < NWIN; n += 256) {
            int d0 = n / 49, r = n % 49, h0 = r / 7, w0 = r % 7;
            int gd = wd * 8 + d0, gh = wh * 7 + h0, gw = ww * 7 + w0;
            int rd = gd < 8 ? 0 : (gd < 12 ? 1 : 2);
            int rh = gh < 7 ? 0 : (gh < 11 ? 1 : 2);
            int rw = gw < 7 ? 0 : (gw < 11 ? 1 : 2);
            lbl[n] = rd * 9 + rh * 3 + rw;
        }
    }
    __syncthreads();

    int warp = tid >> 5, lane = tid & 31;
    float* pw = probs + warp * 4 * NWIN;
    const int d2l = lane & 15, mh = (lane >> 4) * 196;
    const float* biasH = biasE + (size_t)head * NWIN * NWIN;

    for (int bt = 0; bt < 13; bt++) {
        int n0 = warp * 49 + bt * 4;
        int nmax = warp * 49 + 48;
        int nr[4];
#pragma unroll
        for (int r = 0; r < 4; r++) nr[r] = (n0 + r > nmax) ? nmax : n0 + r;

        /* ---- QK with packed dual-fp32 FMA ---- */
        unsigned long long acc2[4][13];
#pragma unroll
        for (int r = 0; r < 4; r++)
#pragma unroll
            for (int j = 0; j < 13; j++) acc2[r][j] = 0ull;
#pragma unroll 4
        for (int d2 = 0; d2 < 16; d2++) {
            unsigned long long q[4];
#pragma unroll
            for (int r = 0; r < 4; r++)
                q[r] = *(const unsigned long long*)&Qs2[nr[r] * 17 + d2];
#pragma unroll
            for (int j = 0; j < 12; j++) {
                unsigned long long k2 = *(const unsigned long long*)&Ks2[(j * 32 + lane) * 17 + d2];
#pragma unroll
                for (int r = 0; r < 4; r++)
                    FMA2(acc2[r][j], q[r], k2);
            }
            if (lane < 8) {
                unsigned long long k2 = *(const unsigned long long*)&Ks2[(384 + lane) * 17 + d2];
#pragma unroll
                for (int r = 0; r < 4; r++)
                    FMA2(acc2[r][12], q[r], k2);
            }
        }

        float invs[4];
#pragma unroll
        for (int r = 0; r < 4; r++) {
            const float* brow_ = biasH + (size_t)nr[r] * NWIN;
            int nl = shifted ? lbl[nr[r]] : 0;
            float mx = -1e30f;
            float sv[13];
#pragma unroll
            for (int j = 0; j < 13; j++) {
                int m = j * 32 + lane;
                float s;
                if (m < NWIN) {
                    float2 a2;
                    memcpy(&a2, &acc2[r][j], 8);
                    s = a2.x + a2.y + __ldg(brow_ + m);
                    if (shifted && lbl[m] != nl) s -= 100.f;
                } else s = -3e38f;
                sv[j] = s;
                mx = fmaxf(mx, s);
            }
#pragma unroll
            for (int o = 16; o; o >>= 1) mx = fmaxf(mx, __shfl_xor_sync(0xffffffffu, mx, o));
            float sum = 0.f;
#pragma unroll
            for (int j = 0; j < 13; j++) {
                int m = j * 32 + lane;
                float e = (m < NWIN) ? __expf(sv[j] - mx) : 0.f;
                sum += e;
                if (m < NWIN) pw[m * 4 + r] = e;
            }
#pragma unroll
            for (int o = 16; o; o >>= 1) sum += __shfl_xor_sync(0xffffffffu, sum, o);
            invs[r] = 1.f / sum;
        }
        __syncwarp();

        /* ---- AV with packed dual-fp32 FMA, LDS.128 probs ---- */
        unsigned long long ox01 = 0ull, ox23 = 0ull, oy01 = 0ull, oy23 = 0ull;
#pragma unroll 4
        for (int m = 0; m < 196; m++) {
            float2 v = Vs2[(m + mh) * 17 + d2l];
            ulonglong2 pp = *(const ulonglong2*)(pw + (m + mh) * 4);
            unsigned long long vx, vy;
            DUP2(vx, v.x);
            DUP2(vy, v.y);
            FMA2(ox01, pp.x, vx);
            FMA2(ox23, pp.y, vx);
            FMA2(oy01, pp.x, vy);
            FMA2(oy23, pp.y, vy);
        }
        float2 o[4];
        UNPK2(o[0].x, o[1].x, ox01);
        UNPK2(o[2].x, o[3].x, ox23);
        UNPK2(o[0].y, o[1].y, oy01);
        UNPK2(o[2].y, o[3].y, oy23);
#pragma unroll
        for (int r = 0; r < 4; r++) {
            o[r].x += __shfl_down_sync(0xffffffffu, o[r].x, 16);
            o[r].y += __shfl_down_sync(0xffffffffu, o[r].y, 16);
        }
        if (lane < 16) {
#pragma unroll
            for (int r = 0; r < 4; r++) {
                float vx = o[r].x * invs[r];
                float vy = o[r].y * invs[r];
                __nv_bfloat16 hx = __float2bfloat16(vx);
                __nv_bfloat16 hy = __float2bfloat16(vy);
                __nv_bfloat16 lx = __float2bfloat16(vx - __bfloat162float(hx));
                __nv_bfloat16 ly = __float2bfloat16(vy - __bfloat162float(hy));
                __nv_bfloat16* op = aout + (size_t)(win * NWIN + nr[r]) * 1536 + head * HD + d2l * 2;
                __nv_bfloat162 hh; hh.x = hx; hh.y = hy;
                __nv_bfloat162 ll; ll.x = lx; ll.y = ly;
                *(__nv_bfloat162*)op = hh;
                *(__nv_bfloat162*)(op + 768) = ll;
            }
        }
        __syncwarp();
    }
}

/* ---------------- conv2 (64 -> 2) + GELU ---------------- */
__global__ void conv2_kernel(const float* __restrict__ T3, const float* __restrict__ w,
                             const float* __restrict__ b, float* __restrict__ O) {
    int t = blockIdx.x * 256 + threadIdx.x;
    if (t >= NT) return;
    const float* r = T3 + (size_t)t * 64;
    float a0 = b[0], a1 = b[1];
#pragma unroll
    for (int k = 0; k < 64; k++) {
        float v = r[k];
        a0 += v * w[k];
        a1 += v * w[64 + k];
    }
    O[t * 2 + 0] = gelu_f(a0);
    O[t * 2 + 1] = gelu_f(a1);
}

__global__ void final_kernel(float* __restrict__ out) {
    int i = blockIdx.x * 256 + threadIdx.x;
    if (i >= NT * 2) return;
    int t = i >> 1, ch = i & 1;
    int b = t / SP, sp = t % SP;
    out[((size_t)(b * 2 + ch)) * SP + sp] = g_O[0][i] * g_O[1][i];
}

/* ---------------- host ---------------- */
extern "C" void kernel_launch(void* const* d_in, const int* in_sizes, int n_in,
                              void* d_out, int out_size) {
    const float* x      = (const float*)d_in[0];
    const float* n1_g   = (const float*)d_in[1];
    const float* n1_b   = (const float*)d_in[2];
    const float* qkv_w  = (const float*)d_in[3];
    const float* qkv_b  = (const float*)d_in[4];
    const float* proj_w = (const float*)d_in[5];
    const float* proj_b = (const float*)d_in[6];
    const float* rpb    = (const float*)d_in[7];
    const float* n2_g   = (const float*)d_in[8];
    const float* n2_b   = (const float*)d_in[9];
    const float* fc1_w  = (const float*)d_in[10];
    const float* fc1_b  = (const float*)d_in[11];
    const float* fc2_w  = (const float*)d_in[12];
    const float* fc2_b  = (const float*)d_in[13];
    const float* hln_g  = (const float*)d_in[14];
    const float* hln_b  = (const float*)d_in[15];
    const float* c1_w   = (const float*)d_in[16];
    const float* c1_b   = (const float*)d_in[17];
    const float* c2_w   = (const float*)d_in[18];
    const float* c2_b   = (const float*)d_in[19];
    const int*   rpi    = (const int*)d_in[20];
    float* out = (float*)d_out;

    float *pXs, *pX, *pQKV, *pT3, *pO, *pBiasE;
    int* pmap;
    __nv_bfloat16 *pWq, *pWp_, *pWf1, *pWf2, *pWc1, *pAp, *pAp2;
    cudaGetSymbolAddress((void**)&pXs,  g_Xs);
    cudaGetSymbolAddress((void**)&pX,   g_X);
    cudaGetSymbolAddress((void**)&pQKV, g_QKV);
    cudaGetSymbolAddress((void**)&pT3,  g_T3);
    cudaGetSymbolAddress((void**)&pO,   g_O);
    cudaGetSymbolAddress((void**)&pBiasE, g_BiasE);
    cudaGetSymbolAddress((void**)&pmap, g_map);
    cudaGetSymbolAddress((void**)&pWq,  g_Wqkv);
    cudaGetSymbolAddress((void**)&pWp_, g_Wproj);
    cudaGetSymbolAddress((void**)&pWf1, g_Wfc1);
    cudaGetSymbolAddress((void**)&pWf2, g_Wfc2);
    cudaGetSymbolAddress((void**)&pWc1, g_Wc1);
    cudaGetSymbolAddress((void**)&pAp,  g_Ap);
    cudaGetSymbolAddress((void**)&pAp2, g_Ap2);

    static cudaStream_t s1 = nullptr;
    static cudaEvent_t evF = nullptr, evJ = nullptr, evP0 = nullptr, evP1 = nullptr;
    if (!s1) {
        cudaStreamCreateWithFlags(&s1, cudaStreamNonBlocking);
        cudaEventCreateWithFlags(&evF, cudaEventDisableTiming);
        cudaEventCreateWithFlags(&evJ, cudaEventDisableTiming);
        cudaEventCreateWithFlags(&evP0, cudaEventDisableTiming);
        cudaEventCreateWithFlags(&evP1, cudaEventDisableTiming);
    }

    const int attn_smem = ATTN2_FLOATS * 4;
    cudaFuncSetAttribute(attn2_kernel, cudaFuncAttributeMaxDynamicSharedMemorySize, attn_smem);
    cudaFuncSetAttribute(gemm_mma<0,0>, cudaFuncAttributeMaxDynamicSharedMemorySize, GSMEM);
    cudaFuncSetAttribute(gemm_mma<1,0>, cudaFuncAttributeMaxDynamicSharedMemorySize, GSMEM);
    cudaFuncSetAttribute(gemm_mma<1,1>, cudaFuncAttributeMaxDynamicSharedMemorySize, GSMEM);

    cudaEventRecord(evF, 0);
    cudaStreamWaitEvent(s1, evF, 0);

    const int biasE_grid = (int)(((size_t)HEADS * NWIN * NWIN + 255) / 256);
    const size_t BE_SZ = (size_t)HEADS * NWIN * NWIN;

    /* setup phase, split across both streams */
    init_maps_kernel<<<(NT + 255) / 256, 256>>>();
    transpose_in_kernel<<<dim3(SP / 32, CDIM / 32, B_), dim3(32, 8)>>>(x, pXs);
    pack_w_kernel<<<dim3((2304 * 768 + 255) / 256, 1, 4), 256>>>(
        qkv_w, pWq, 2304, 2304, 768, (size_t)2304 * 768, (size_t)EW_QKV);
    pack_w_kernel<<<dim3((768 * 768 + 255) / 256, 1, 4), 256>>>(
        proj_w, pWp_, 768, 768, 768, (size_t)768 * 768, (size_t)EW_PROJ);
    pack_w_kernel<<<dim3((128 * 768 + 255) / 256, 1, 2), 256>>>(
        c1_w, pWc1, 64, 128, 768, (size_t)64 * 768, (size_t)EW_C1);
    bias_exp_kernel<<<biasE_grid, 256>>>(rpb + 0 * RPB_SZ * HEADS, rpi, pBiasE + 0 * BE_SZ);
    bias_exp_kernel<<<biasE_grid, 256>>>(rpb + 1 * RPB_SZ * HEADS, rpi, pBiasE + 1 * BE_SZ);
    cudaEventRecord(evP0, 0);
    pack_w_kernel<<<dim3((3072 * 768 + 255) / 256, 1, 4), 256, 0, s1>>>(
        fc1_w, pWf1, 3072, 3072, 768, (size_t)3072 * 768, (size_t)EW_FC1);
    pack_w_kernel<<<dim3((768 * 3072 + 255) / 256, 1, 4), 256, 0, s1>>>(
        fc2_w, pWf2, 768, 768, 3072, (size_t)768 * 3072, (size_t)EW_FC2);
    bias_exp_kernel<<<biasE_grid, 256, 0, s1>>>(rpb + 2 * RPB_SZ * HEADS, rpi, pBiasE + 2 * BE_SZ);
    bias_exp_kernel<<<biasE_grid, 256, 0, s1>>>(rpb + 3 * RPB_SZ * HEADS, rpi, pBiasE + 3 * BE_SZ);
    cudaEventRecord(evP1, s1);
    cudaStreamWaitEvent(0, evP1, 0);
    cudaStreamWaitEvent(s1, evP0, 0);

    for (int br = 0; br < 2; br++) {
        cudaStream_t st = br ? s1 : (cudaStream_t)0;
        float* bX   = pX   + (size_t)br * NT * CDIM;
        float* bQKV = pQKV + (size_t)br * NT * 3 * CDIM;
        float* bT3  = pT3  + (size_t)br * NT * 64;
        __nv_bfloat16* bAp  = pAp  + (size_t)br * NT * 1536;
        __nv_bfloat16* bAp2 = pAp2 + (size_t)br * NT * 6144;

        for (int bl = 0; bl < 2; bl++) {
            int s = bl;
            size_t wo = (size_t)(br * 2 + bl);
            const float* inX  = (bl == 0) ? pXs : bX;   /* block0 reads shared transpose */
            float* bBE = pBiasE + wo * BE_SZ;
            ln_pack_kernel<<<NT, 256, 0, st>>>(inX, n1_g + wo * CDIM, n1_b + wo * CDIM, bAp, pmap + s * NT);
            gemm_mma<0,0><<<dim3(18, 49), 256, GSMEM, st>>>(
                bAp, pWq + wo * EW_QKV, qkv_b + wo * 2304, bQKV,
                nullptr, nullptr, 2304, 768);
            attn2_kernel<<<dim3(HEADS, BW), 256, attn_smem, st>>>(
                bQKV, bBE, bAp, s);
            gemm_mma<0,0><<<dim3(6, 49), 256, GSMEM, st>>>(
                bAp, pWp_ + wo * EW_PROJ, proj_b + wo * CDIM, bX,
                inX, pmap + s * NT, 768, 768);
            ln_pack_kernel<<<NT, 256, 0, st>>>(bX, n2_g + wo * CDIM, n2_b + wo * CDIM, bAp, nullptr);
            gemm_mma<1,1><<<dim3(24, 49), 256, GSMEM, st>>>(
                bAp, pWf1 + wo * EW_FC1, fc1_b + wo * 3072, (float*)bAp2,
                nullptr, nullptr, 3072, 768);
            gemm_mma<0,0><<<dim3(6, 49), 256, GSMEM, st>>>(
                bAp2, pWf2 + wo * EW_FC2, fc2_b + wo * CDIM, bX,
                bX, nullptr, 768, 3072);
        }
        ln_pack_kernel<<<NT, 256, 0, st>>>(bX, hln_g + br * CDIM, hln_b + br * CDIM, bAp, nullptr);
        gemm_mma<1,0><<<dim3(1, 49), 256, GSMEM, st>>>(
            bAp, pWc1 + br * EW_C1, c1_b + br * 64, bT3,
            nullptr, nullptr, 64, 768);
        conv2_kernel<<<(NT + 255) / 256, 256, 0, st>>>(bT3, c2_w + br * 2 * 64, c2_b + br * 2,
                                                       pO + (size_t)br * NT * 2);
    }

    cudaEventRecord(evJ, s1);
    cudaStreamWaitEvent(0, evJ, 0);
    final_kernel<<<(NT * 2 + 255) / 256, 256>>>(out);
}

// round 15
// speedup vs baseline: 2.1620x; 1.0207x over previous
#include <cuda_runtime.h>
#include <cuda_bf16.h>
#include <math.h>
#include <stdint.h>
#include <string.h>

#define B_    2
#define DD    16
#define HH    14
#define WWQ   14
#define CDIM  768
#define SP    (DD*HH*WWQ)      /* 3136 */
#define NT    (B_*SP)          /* 6272 tokens */
#define NWIN  392
#define BW    16
#define HEADS 24
#define HD    32
#define RPB_SZ 2535

/* packed weight element counts (bf16): [Wh | Wl], row stride 2K */
#define EW_QKV  (2304u*1536u)
#define EW_PROJ (768u*1536u)
#define EW_FC1  (3072u*1536u)
#define EW_FC2  (768u*6144u)
#define EW_C1   (128u*1536u)

/* ---------------- scratch ---------------- */
__device__ float g_Xs [NT*CDIM];                 /* shared transposed input */
__device__ float g_X  [2][NT*CDIM];
__device__ float g_QKV[2][NT*3*CDIM];
__device__ float g_T3 [2][NT*64];
__device__ float g_O  [2][NT*2];
__device__ int   g_map[2][NT];
__device__ float g_BiasE[4][(size_t)HEADS*NWIN*NWIN];   /* per (br,bl) expanded bias */
__device__ __nv_bfloat16 g_Wqkv [4*EW_QKV];
__device__ __nv_bfloat16 g_Wproj[4*EW_PROJ];
__device__ __nv_bfloat16 g_Wfc1 [4*EW_FC1];
__device__ __nv_bfloat16 g_Wfc2 [4*EW_FC2];
__device__ __nv_bfloat16 g_Wc1  [2*EW_C1];
__device__ __nv_bfloat16 g_Ap [2][(size_t)NT*1536];
__device__ __nv_bfloat16 g_Ap2[2][(size_t)NT*6144];

__device__ __forceinline__ float gelu_f(float x) {
    return 0.5f * x * (1.0f + erff(x * 0.70710678118654752f));
}
__device__ __forceinline__ uint32_t smem_u32(const void* p) {
    uint32_t a;
    asm("{ .reg .u64 t; cvta.to.shared.u64 t, %1; cvt.u32.u64 %0, t; }" : "=r"(a) : "l"(p));
    return a;
}
#define CP16(s, g) \
    asm volatile("cp.async.cg.shared.global [%0], [%1], 16;" :: "r"(s), "l"(g) : "memory")
#define CP_COMMIT() asm volatile("cp.async.commit_group;" ::: "memory")
#define CP_WAIT1()  asm volatile("cp.async.wait_group 1;" ::: "memory")
#define LDSM4(r, addr) \
    asm volatile("ldmatrix.sync.aligned.m8n8.x4.shared.b16 {%0,%1,%2,%3}, [%4];" \
        : "=r"((r)[0]), "=r"((r)[1]), "=r"((r)[2]), "=r"((r)[3]) : "r"(addr))
#define MMA16816(c, a, b0, b1) \
    asm volatile("mma.sync.aligned.m16n8k16.row.col.f32.bf16.bf16.f32 " \
        "{%0,%1,%2,%3}, {%4,%5,%6,%7}, {%8,%9}, {%0,%1,%2,%3};" \
        : "+f"((c)[0]), "+f"((c)[1]), "+f"((c)[2]), "+f"((c)[3]) \
        : "r"((a)[0]), "r"((a)[1]), "r"((a)[2]), "r"((a)[3]), "r"(b0), "r"(b1))
/* packed dual fp32 FMA: d = a*b + d (elementwise on 2 lanes) */
#define FMA2(d, a, b) \
    asm("fma.rn.f32x2 %0, %1, %2, %0;" : "+l"(d) : "l"(a), "l"(b))
#define DUP2(d, f) \
    asm("mov.b64 %0, {%1, %1};" : "=l"(d) : "f"(f))
#define UNPK2(lo, hi, v) \
    asm("mov.b64 {%0, %1}, %2;" : "=f"(lo), "=f"(hi) : "l"(v))

/* ---------------- window/roll index maps ---------------- */
__global__ void init_maps_kernel() {
    int wt = blockIdx.x * blockDim.x + threadIdx.x;
    if (wt >= NT) return;
    int win = wt / NWIN, n = wt % NWIN;
    int b = win >> 3, wr = win & 7;
    int wd = wr >> 2, wh = (wr >> 1) & 1, ww = wr & 1;
    int d0 = n / 49, r = n % 49, h0 = r / 7, w0 = r % 7;
    for (int s = 0; s < 2; s++) {
        int sd = s ? 4 : 0, sh = s ? 3 : 0, sw = s ? 3 : 0;
        int gd = (wd * 8 + d0 + sd) & 15;
        int gh = (wh * 7 + h0 + sh) % 14;
        int gw = (ww * 7 + w0 + sw) % 14;
        g_map[s][wt] = ((b * DD + gd) * HH + gh) * WWQ + gw;
    }
}

/* ---------------- expand rel-pos bias: biasE[h][n][m] = rpb[rpi[n][m]][h] ---------------- */
__global__ void bias_exp_kernel(const float* __restrict__ rpb, const int* __restrict__ rpi,
                                float* __restrict__ dst) {
    size_t idx = (size_t)blockIdx.x * 256 + threadIdx.x;
    if (idx >= (size_t)HEADS * NWIN * NWIN) return;
    int m = (int)(idx % NWIN);
    int rest = (int)(idx / NWIN);
    int n = rest % NWIN, h = rest / NWIN;
    dst[idx] = rpb[(size_t)rpi[n * NWIN + m] * HEADS + h];
}

/* ---------------- (B,C,D,H,W) -> (token, C) transpose ---------------- */
__global__ void transpose_in_kernel(const float* __restrict__ x, float* __restrict__ X) {
    __shared__ float tile[32][33];
    int b = blockIdx.z;
    int s0 = blockIdx.x * 32, c0 = blockIdx.y * 32;
    int tx = threadIdx.x, ty = threadIdx.y;
#pragma unroll
    for (int i = 0; i < 32; i += 8)
        tile[ty + i][tx] = x[((size_t)(b * CDIM + c0 + ty + i)) * SP + s0 + tx];
    __syncthreads();
#pragma unroll
    for (int i = 0; i < 32; i += 8)
        X[((size_t)(b * SP + s0 + ty + i)) * CDIM + c0 + tx] = tile[tx][ty + i];
}

/* ------- LayerNorm over C=768 -> packed bf16 [h | l], single-pass reduction ------- */
__global__ void ln_pack_kernel(const float* __restrict__ in, const float* __restrict__ gamma,
                               const float* __restrict__ beta, __nv_bfloat16* __restrict__ dst,
                               const int* __restrict__ map) {
    int t = blockIdx.x;
    int src = map ? map[t] : t;
    const float* row = in + (size_t)src * CDIM;
    __nv_bfloat16* orow = dst + (size_t)t * 1536;
    int tid = threadIdx.x;
    float v0 = row[tid], v1 = row[tid + 256], v2 = row[tid + 512];
    float s  = v0 + v1 + v2;
    float sq = v0 * v0 + v1 * v1 + v2 * v2;
    __shared__ float red[16];
#pragma unroll
    for (int o = 16; o; o >>= 1) {
        s  += __shfl_xor_sync(0xffffffffu, s, o);
        sq += __shfl_xor_sync(0xffffffffu, sq, o);
    }
    if ((tid & 31) == 0) { red[tid >> 5] = s; red[8 + (tid >> 5)] = sq; }
    __syncthreads();
    if (tid < 32) {
        float a = (tid < 8) ? red[tid] : 0.f;
        float b = (tid < 8) ? red[8 + tid] : 0.f;
#pragma unroll
        for (int o = 4; o; o >>= 1) {
            a += __shfl_xor_sync(0xffffffffu, a, o);
            b += __shfl_xor_sync(0xffffffffu, b, o);
        }
        if (tid == 0) { red[0] = a; red[8] = b; }
    }
    __syncthreads();
    float mu  = red[0] * (1.0f / CDIM);
    float var = red[8] * (1.0f / CDIM) - mu * mu;
    float inv = rsqrtf(var + 1e-5f);
#pragma unroll
    for (int q = 0; q < 3; q++) {
        int c = tid + q * 256;
        float vv = (q == 0 ? v0 : q == 1 ? v1 : v2);
        float v = (vv - mu) * inv * gamma[c] + beta[c];
        __nv_bfloat16 h = __float2bfloat16(v);
        __nv_bfloat16 l = __float2bfloat16(v - __bfloat162float(h));
        orow[c] = h;
        orow[768 + c] = l;
    }
}

/* ------- pack weights: fp32 [Nreal][K] -> bf16 [Npad][2K] = [Wh | Wl] ------- */
__global__ void pack_w_kernel(const float* __restrict__ src, __nv_bfloat16* __restrict__ dst,
                              int Nreal, int Npad, int K, size_t srcStride, size_t dstStride) {
    int z = blockIdx.z;
    src += (size_t)z * srcStride;
    dst += (size_t)z * dstStride;
    int idx = blockIdx.x * 256 + threadIdx.x;
    if (idx >= Npad * K) return;
    int k = idx % K, n = idx / K;
    float v = (n < Nreal) ? src[(size_t)n * K + k] : 0.f;
    __nv_bfloat16 h = __float2bfloat16(v);
    __nv_bfloat16 l = __float2bfloat16(v - __bfloat162float(h));
    size_t ro = (size_t)n * 2 * K;
    dst[ro + k] = h;
    dst[ro + K + k] = l;
}

/* ---------------- bf16 mma.sync GEMM (8 warps, 64x32 warp tile, 3-stage, 2 CTA/SM) ---------------- */
#define GSMEM (3 * 32768)
template<int ACT, int PACK>
__global__ void __launch_bounds__(256) gemm_mma(
    const __nv_bfloat16* __restrict__ A, const __nv_bfloat16* __restrict__ B,
    const float* __restrict__ bias, float* __restrict__ Out,
    const float* __restrict__ Res, const int* __restrict__ mapC,
    int Nreal, int K) {
    extern __shared__ char smraw[];
    uint32_t sbase = smem_u32(smraw);
    const int tid = threadIdx.x;
    const int nt = blockIdx.x, mt = blockIdx.y;
    const int KI3 = K >> 6;
    const int KT = 3 * KI3;
    const int K2 = 2 * K;

    const int lr0 = tid >> 3;
    const int lkg = tid & 7;
    const uint32_t lswz = (uint32_t)((lkg ^ (lr0 & 7)) * 16);
    const __nv_bfloat16* Ag = A + (size_t)(mt * 128 + lr0) * K2 + lkg * 8;
    const __nv_bfloat16* Bg = B + (size_t)(nt * 128 + lr0) * K2 + lkg * 8;
    uint32_t soffs[4];
#pragma unroll
    for (int i = 0; i < 4; i++) soffs[i] = (uint32_t)((lr0 + 32 * i) * 128) + lswz;

    const int lane = tid & 31, wid = tid >> 5;
    const int wm = wid & 1, wn = wid >> 1;
    const int arow = wm * 64 + (lane & 15);
    const int khalfA = lane >> 4;
    const int ar7 = arow & 7;
    uint32_t aoffs[4];
#pragma unroll
    for (int i = 0; i < 4; i++) aoffs[i] = (uint32_t)((arow + 16 * i) * 128);
    const int brow = wn * 32 + (lane & 7) + ((lane >> 4) << 3);
    const int kaddB = (lane >> 3) & 1;
    const int br7 = brow & 7;
    uint32_t boffs[2];
#pragma unroll
    for (int p = 0; p < 2; p++) boffs[p] = (uint32_t)(16384 + (brow + 16 * p) * 128);

    float acc[4][4][4];
#pragma unroll
    for (int i = 0; i < 4; i++)
#pragma unroll
        for (int j = 0; j < 4; j++)
#pragma unroll
            for (int r = 0; r < 4; r++) acc[i][j][r] = 0.f;

#pragma unroll
    for (int pl = 0; pl < 2; pl++) {
        uint32_t sa = sbase + pl * 32768, sb = sa + 16384;
        const __nv_bfloat16* ga = Ag + (size_t)pl * 64;
        const __nv_bfloat16* gb = Bg + (size_t)pl * 64;
#pragma unroll
        for (int i = 0; i < 4; i++) {
            CP16(sa + soffs[i], ga + (size_t)(32 * i) * K2);
            CP16(sb + soffs[i], gb + (size_t)(32 * i) * K2);
        }
        CP_COMMIT();
    }

    for (int kt = 0; kt < KT; kt++) {
        CP_WAIT1();
        __syncthreads();
        int s = kt - (kt / 3) * 3;
        int nk = kt + 2;
        if (nk < KT) {
            int s2 = nk - (nk / 3) * 3;
            int asl = (nk < KI3) ? nk : nk - KI3;
            int bsl = (nk < 2 * KI3) ? nk : nk - 2 * KI3;
            uint32_t sa = sbase + s2 * 32768, sb = sa + 16384;
            const __nv_bfloat16* ga = Ag + (size_t)asl * 64;
            const __nv_bfloat16* gb = Bg + (size_t)bsl * 64;
#pragma unroll
            for (int i = 0; i < 4; i++) {
                CP16(sa + soffs[i], ga + (size_t)(32 * i) * K2);
                CP16(sb + soffs[i], gb + (size_t)(32 * i) * K2);
            }
        }
        CP_COMMIT();
        uint32_t st = sbase + s * 32768;
#pragma unroll
        for (int ks = 0; ks < 4; ks++) {
            uint32_t a[4][4], b[2][4];
            uint32_t aswz = (uint32_t)(((2 * ks + khalfA) ^ ar7) * 16);
#pragma unroll
            for (int i = 0; i < 4; i++) LDSM4(a[i], st + aoffs[i] + aswz);
            uint32_t bswz = (uint32_t)(((2 * ks + kaddB) ^ br7) * 16);
#pragma unroll
            for (int p = 0; p < 2; p++) LDSM4(b[p], st + boffs[p] + bswz);
#pragma unroll
            for (int i = 0; i < 4; i++)
#pragma unroll
                for (int j = 0; j < 4; j++)
                    MMA16816(acc[i][j], a[i], b[j >> 1][(j & 1) * 2], b[j >> 1][(j & 1) * 2 + 1]);
        }
    }

    const int g = lane >> 2, tg = lane & 3;
#pragma unroll
    for (int i = 0; i < 4; i++) {
#pragma unroll
        for (int rh = 0; rh < 2; rh++) {
            int m = mt * 128 + wm * 64 + i * 16 + g + rh * 8;
            if (PACK == 0) {
                int orow = mapC ? mapC[m] : m;
                float* op = Out + (size_t)orow * Nreal;
                const float* rp = Res ? Res + (size_t)orow * Nreal : nullptr;
#pragma unroll
                for (int j = 0; j < 4; j++) {
                    int col = nt * 128 + wn * 32 + j * 8 + tg * 2;
                    if (col < Nreal) {
                        float v0 = acc[i][j][rh * 2 + 0] + bias[col];
                        float v1 = acc[i][j][rh * 2 + 1] + bias[col + 1];
                        if (ACT == 1) { v0 = gelu_f(v0); v1 = gelu_f(v1); }
                        if (rp) { v0 += rp[col]; v1 += rp[col + 1]; }
                        float2 o2 = make_float2(v0, v1);
                        *(float2*)(op + col) = o2;
                    }
                }
            } else {
                __nv_bfloat16* op = (__nv_bfloat16*)Out + (size_t)m * 2 * Nreal;
#pragma unroll
                for (int j = 0; j < 4; j++) {
                    int col = nt * 128 + wn * 32 + j * 8 + tg * 2;
                    float v0 = acc[i][j][rh * 2 + 0] + bias[col];
                    float v1 = acc[i][j][rh * 2 + 1] + bias[col + 1];
                    if (ACT == 1) { v0 = gelu_f(v0); v1 = gelu_f(v1); }
                    __nv_bfloat16 h0 = __float2bfloat16(v0);
                    __nv_bfloat16 h1 = __float2bfloat16(v1);
                    __nv_bfloat16 l0 = __float2bfloat16(v0 - __bfloat162float(h0));
                    __nv_bfloat16 l1 = __float2bfloat16(v1 - __bfloat162float(h1));
                    __nv_bfloat162 hh; hh.x = h0; hh.y = h1;
                    __nv_bfloat162 ll; ll.x = l0; ll.y = l1;
                    *(__nv_bfloat162*)(op + col) = hh;
                    *(__nv_bfloat162*)(op + Nreal + col) = ll;
                }
            }
        }
    }
}

/* ---------------- fused window attention v8: f32x2 QK/AV, prefetched bias ---------------- */
#define ATTN2_FLOATS (3*NWIN*17*2 + 8*4*NWIN + NWIN)
__global__ void __launch_bounds__(256) attn2_kernel(
    const float* __restrict__ qkv, const float* __restrict__ biasE,
    __nv_bfloat16* __restrict__ aout, int shifted) {
    extern __shared__ float sm[];
    float2* Qs2 = (float2*)sm;
    float2* Ks2 = Qs2 + NWIN * 17;
    float2* Vs2 = Ks2 + NWIN * 17;
    float* probs = (float*)(Vs2 + NWIN * 17);
    int*   lbl   = (int*)(probs + 8 * 4 * NWIN);
    int head = blockIdx.x, win = blockIdx.y;
    int tid = threadIdx.x;
    const float scale = 0.17677669529663687f;

    for (int idx = tid; idx < NWIN * 16; idx += 256) {
        int n = idx >> 4, d2 = idx & 15;
        size_t base = ((size_t)(win * NWIN + n)) * (3 * CDIM) + head * HD + d2 * 2;
        float2 q = *(const float2*)(qkv + base);
        q.x *= scale; q.y *= scale;
        Qs2[n * 17 + d2] = q;
        Ks2[n * 17 + d2] = *(const float2*)(qkv + base + CDIM);
        Vs2[n * 17 + d2] = *(const float2*)(qkv + base + 2 * CDIM);
    }
    if (shifted) {
        int wr = win & 7, wd = wr >> 2, wh = (wr >> 1) & 1, ww = wr & 1;
        for (int n = tid; n < NWIN; n += 256) {
            int d0 = n / 49, r = n % 49, h0 = r / 7, w0 = r % 7;
            int gd = wd * 8 + d0, gh = wh * 7 + h0, gw = ww * 7 + w0;
            int rd = gd < 8 ? 0 : (gd < 12 ? 1 : 2);
            int rh = gh < 7 ? 0 : (gh < 11 ? 1 : 2);
            int rw = gw < 7 ? 0 : (gw < 11 ? 1 : 2);
            lbl[n] = rd * 9 + rh * 3 + rw;
        }
    }
    __syncthreads();

    int warp = tid >> 5, lane = tid & 31;
    float* pw = probs + warp * 4 * NWIN;
    const int d2l = lane & 15, mh = (lane >> 4) * 196;
    const float* biasH = biasE + (size_t)head * NWIN * NWIN;

    for (int bt = 0; bt < 13; bt++) {
        int n0 = warp * 49 + bt * 4;
        int nmax = warp * 49 + 48;
        int nr[4];
#pragma unroll
        for (int r = 0; r < 4; r++) nr[r] = (n0 + r > nmax) ? nmax : n0 + r;

        /* ---- prefetch bias for all 4 rows x 13 columns (overlaps with QK) ---- */
        float bv[4][13];
#pragma unroll
        for (int r = 0; r < 4; r++) {
            const float* brow_ = biasH + (size_t)nr[r] * NWIN;
#pragma unroll
            for (int j = 0; j < 13; j++) {
                int m = j * 32 + lane;
                bv[r][j] = (m < NWIN) ? __ldg(brow_ + m) : 0.f;
            }
        }

        /* ---- QK with packed dual-fp32 FMA ---- */
        unsigned long long acc2[4][13];
#pragma unroll
        for (int r = 0; r < 4; r++)
#pragma unroll
            for (int j = 0; j < 13; j++) acc2[r][j] = 0ull;
#pragma unroll 4
        for (int d2 = 0; d2 < 16; d2++) {
            unsigned long long q[4];
#pragma unroll
            for (int r = 0; r < 4; r++)
                q[r] = *(const unsigned long long*)&Qs2[nr[r] * 17 + d2];
#pragma unroll
            for (int j = 0; j < 12; j++) {
                unsigned long long k2 = *(const unsigned long long*)&Ks2[(j * 32 + lane) * 17 + d2];
#pragma unroll
                for (int r = 0; r < 4; r++)
                    FMA2(acc2[r][j], q[r], k2);
            }
            if (lane < 8) {
                unsigned long long k2 = *(const unsigned long long*)&Ks2[(384 + lane) * 17 + d2];
#pragma unroll
                for (int r = 0; r < 4; r++)
                    FMA2(acc2[r][12], q[r], k2);
            }
        }

        float invs[4];
#pragma unroll
        for (int r = 0; r < 4; r++) {
            int nl = shifted ? lbl[nr[r]] : 0;
            float mx = -1e30f;
            float sv[13];
#pragma unroll
            for (int j = 0; j < 13; j++) {
                int m = j * 32 + lane;
                float s;
                if (m < NWIN) {
                    float2 a2;
                    memcpy(&a2, &acc2[r][j], 8);
                    s = a2.x + a2.y + bv[r][j];
                    if (shifted && lbl[m] != nl) s -= 100.f;
                } else s = -3e38f;
                sv[j] = s;
                mx = fmaxf(mx, s);
            }
#pragma unroll
            for (int o = 16; o; o >>= 1) mx = fmaxf(mx, __shfl_xor_sync(0xffffffffu, mx, o));
            float sum = 0.f;
#pragma unroll
            for (int j = 0; j < 13; j++) {
                int m = j * 32 + lane;
                float e = (m < NWIN) ? __expf(sv[j] - mx) : 0.f;
                sum += e;
                if (m < NWIN) pw[m * 4 + r] = e;
            }
#pragma unroll
            for (int o = 16; o; o >>= 1) sum += __shfl_xor_sync(0xffffffffu, sum, o);
            invs[r] = 1.f / sum;
        }
        __syncwarp();

        /* ---- AV with packed dual-fp32 FMA, LDS.128 probs ---- */
        unsigned long long ox01 = 0ull, ox23 = 0ull, oy01 = 0ull, oy23 = 0ull;
#pragma unroll 8
        for (int m = 0; m < 196; m++) {
            float2 v = Vs2[(m + mh) * 17 + d2l];
            ulonglong2 pp = *(const ulonglong2*)(pw + (m + mh) * 4);
            unsigned long long vx, vy;
            DUP2(vx, v.x);
            DUP2(vy, v.y);
            FMA2(ox01, pp.x, vx);
            FMA2(ox23, pp.y, vx);
            FMA2(oy01, pp.x, vy);
            FMA2(oy23, pp.y, vy);
        }
        float2 o[4];
        UNPK2(o[0].x, o[1].x, ox01);
        UNPK2(o[2].x, o[3].x, ox23);
        UNPK2(o[0].y, o[1].y, oy01);
        UNPK2(o[2].y, o[3].y, oy23);
#pragma unroll
        for (int r = 0; r < 4; r++) {
            o[r].x += __shfl_down_sync(0xffffffffu, o[r].x, 16);
            o[r].y += __shfl_down_sync(0xffffffffu, o[r].y, 16);
        }
        if (lane < 16) {
#pragma unroll
            for (int r = 0; r < 4; r++) {
                float vx = o[r].x * invs[r];
                float vy = o[r].y * invs[r];
                __nv_bfloat16 hx = __float2bfloat16(vx);
                __nv_bfloat16 hy = __float2bfloat16(vy);
                __nv_bfloat16 lx = __float2bfloat16(vx - __bfloat162float(hx));
                __nv_bfloat16 ly = __float2bfloat16(vy - __bfloat162float(hy));
                __nv_bfloat16* op = aout + (size_t)(win * NWIN + nr[r]) * 1536 + head * HD + d2l * 2;
                __nv_bfloat162 hh; hh.x = hx; hh.y = hy;
                __nv_bfloat162 ll; ll.x = lx; ll.y = ly;
                *(__nv_bfloat162*)op = hh;
                *(__nv_bfloat162*)(op + 768) = ll;
            }
        }
        __syncwarp();
    }
}

/* ---------------- conv2 (64 -> 2) + GELU ---------------- */
__global__ void conv2_kernel(const float* __restrict__ T3, const float* __restrict__ w,
                             const float* __restrict__ b, float* __restrict__ O) {
    int t = blockIdx.x * 256 + threadIdx.x;
    if (t >= NT) return;
    const float* r = T3 + (size_t)t * 64;
    float a0 = b[0], a1 = b[1];
#pragma unroll
    for (int k = 0; k < 64; k++) {
        float v = r[k];
        a0 += v * w[k];
        a1 += v * w[64 + k];
    }
    O[t * 2 + 0] = gelu_f(a0);
    O[t * 2 + 1] = gelu_f(a1);
}

__global__ void final_kernel(float* __restrict__ out) {
    int i = blockIdx.x * 256 + threadIdx.x;
    if (i >= NT * 2) return;
    int t = i >> 1, ch = i & 1;
    int b = t / SP, sp = t % SP;
    out[((size_t)(b * 2 + ch)) * SP + sp] = g_O[0][i] * g_O[1][i];
}

/* ---------------- host ---------------- */
extern "C" void kernel_launch(void* const* d_in, const int* in_sizes, int n_in,
                              void* d_out, int out_size) {
    const float* x      = (const float*)d_in[0];
    const float* n1_g   = (const float*)d_in[1];
    const float* n1_b   = (const float*)d_in[2];
    const float* qkv_w  = (const float*)d_in[3];
    const float* qkv_b  = (const float*)d_in[4];
    const float* proj_w = (const float*)d_in[5];
    const float* proj_b = (const float*)d_in[6];
    const float* rpb    = (const float*)d_in[7];
    const float* n2_g   = (const float*)d_in[8];
    const float* n2_b   = (const float*)d_in[9];
    const float* fc1_w  = (const float*)d_in[10];
    const float* fc1_b  = (const float*)d_in[11];
    const float* fc2_w  = (const float*)d_in[12];
    const float* fc2_b  = (const float*)d_in[13];
    const float* hln_g  = (const float*)d_in[14];
    const float* hln_b  = (const float*)d_in[15];
    const float* c1_w   = (const float*)d_in[16];
    const float* c1_b   = (const float*)d_in[17];
    const float* c2_w   = (const float*)d_in[18];
    const float* c2_b   = (const float*)d_in[19];
    const int*   rpi    = (const int*)d_in[20];
    float* out = (float*)d_out;

    float *pXs, *pX, *pQKV, *pT3, *pO, *pBiasE;
    int* pmap;
    __nv_bfloat16 *pWq, *pWp_, *pWf1, *pWf2, *pWc1, *pAp, *pAp2;
    cudaGetSymbolAddress((void**)&pXs,  g_Xs);
    cudaGetSymbolAddress((void**)&pX,   g_X);
    cudaGetSymbolAddress((void**)&pQKV, g_QKV);
    cudaGetSymbolAddress((void**)&pT3,  g_T3);
    cudaGetSymbolAddress((void**)&pO,   g_O);
    cudaGetSymbolAddress((void**)&pBiasE, g_BiasE);
    cudaGetSymbolAddress((void**)&pmap, g_map);
    cudaGetSymbolAddress((void**)&pWq,  g_Wqkv);
    cudaGetSymbolAddress((void**)&pWp_, g_Wproj);
    cudaGetSymbolAddress((void**)&pWf1, g_Wfc1);
    cudaGetSymbolAddress((void**)&pWf2, g_Wfc2);
    cudaGetSymbolAddress((void**)&pWc1, g_Wc1);
    cudaGetSymbolAddress((void**)&pAp,  g_Ap);
    cudaGetSymbolAddress((void**)&pAp2, g_Ap2);

    static cudaStream_t s1 = nullptr;
    static cudaEvent_t evF = nullptr, evJ = nullptr, evP0 = nullptr, evP1 = nullptr;
    if (!s1) {
        cudaStreamCreateWithFlags(&s1, cudaStreamNonBlocking);
        cudaEventCreateWithFlags(&evF, cudaEventDisableTiming);
        cudaEventCreateWithFlags(&evJ, cudaEventDisableTiming);
        cudaEventCreateWithFlags(&evP0, cudaEventDisableTiming);
        cudaEventCreateWithFlags(&evP1, cudaEventDisableTiming);
    }

    const int attn_smem = ATTN2_FLOATS * 4;
    cudaFuncSetAttribute(attn2_kernel, cudaFuncAttributeMaxDynamicSharedMemorySize, attn_smem);
    cudaFuncSetAttribute(gemm_mma<0,0>, cudaFuncAttributeMaxDynamicSharedMemorySize, GSMEM);
    cudaFuncSetAttribute(gemm_mma<1,0>, cudaFuncAttributeMaxDynamicSharedMemorySize, GSMEM);
    cudaFuncSetAttribute(gemm_mma<1,1>, cudaFuncAttributeMaxDynamicSharedMemorySize, GSMEM);

    cudaEventRecord(evF, 0);
    cudaStreamWaitEvent(s1, evF, 0);

    const int biasE_grid = (int)(((size_t)HEADS * NWIN * NWIN + 255) / 256);
    const size_t BE_SZ = (size_t)HEADS * NWIN * NWIN;

    /* setup phase, split across both streams */
    init_maps_kernel<<<(NT + 255) / 256, 256>>>();
    transpose_in_kernel<<<dim3(SP / 32, CDIM / 32, B_), dim3(32, 8)>>>(x, pXs);
    pack_w_kernel<<<dim3((2304 * 768 + 255) / 256, 1, 4), 256>>>(
        qkv_w, pWq, 2304, 2304, 768, (size_t)2304 * 768, (size_t)EW_QKV);
    pack_w_kernel<<<dim3((768 * 768 + 255) / 256, 1, 4), 256>>>(
        proj_w, pWp_, 768, 768, 768, (size_t)768 * 768, (size_t)EW_PROJ);
    pack_w_kernel<<<dim3((128 * 768 + 255) / 256, 1, 2), 256>>>(
        c1_w, pWc1, 64, 128, 768, (size_t)64 * 768, (size_t)EW_C1);
    bias_exp_kernel<<<biasE_grid, 256>>>(rpb + 0 * RPB_SZ * HEADS, rpi, pBiasE + 0 * BE_SZ);
    bias_exp_kernel<<<biasE_grid, 256>>>(rpb + 1 * RPB_SZ * HEADS, rpi, pBiasE + 1 * BE_SZ);
    cudaEventRecord(evP0, 0);
    pack_w_kernel<<<dim3((3072 * 768 + 255) / 256, 1, 4), 256, 0, s1>>>(
        fc1_w, pWf1, 3072, 3072, 768, (size_t)3072 * 768, (size_t)EW_FC1);
    pack_w_kernel<<<dim3((768 * 3072 + 255) / 256, 1, 4), 256, 0, s1>>>(
        fc2_w, pWf2, 768, 768, 3072, (size_t)768 * 3072, (size_t)EW_FC2);
    bias_exp_kernel<<<biasE_grid, 256, 0, s1>>>(rpb + 2 * RPB_SZ * HEADS, rpi, pBiasE + 2 * BE_SZ);
    bias_exp_kernel<<<biasE_grid, 256, 0, s1>>>(rpb + 3 * RPB_SZ * HEADS, rpi, pBiasE + 3 * BE_SZ);
    cudaEventRecord(evP1, s1);
    cudaStreamWaitEvent(0, evP1, 0);
    cudaStreamWaitEvent(s1, evP0, 0);

    for (int br = 0; br < 2; br++) {
        cudaStream_t st = br ? s1 : (cudaStream_t)0;
        float* bX   = pX   + (size_t)br * NT * CDIM;
        float* bQKV = pQKV + (size_t)br * NT * 3 * CDIM;
        float* bT3  = pT3  + (size_t)br * NT * 64;
        __nv_bfloat16* bAp  = pAp  + (size_t)br * NT * 1536;
        __nv_bfloat16* bAp2 = pAp2 + (size_t)br * NT * 6144;

        for (int bl = 0; bl < 2; bl++) {
            int s = bl;
            size_t wo = (size_t)(br * 2 + bl);
            const float* inX  = (bl == 0) ? pXs : bX;   /* block0 reads shared transpose */
            float* bBE = pBiasE + wo * BE_SZ;
            ln_pack_kernel<<<NT, 256, 0, st>>>(inX, n1_g + wo * CDIM, n1_b + wo * CDIM, bAp, pmap + s * NT);
            gemm_mma<0,0><<<dim3(18, 49), 256, GSMEM, st>>>(
                bAp, pWq + wo * EW_QKV, qkv_b + wo * 2304, bQKV,
                nullptr, nullptr, 2304, 768);
            attn2_kernel<<<dim3(HEADS, BW), 256, attn_smem, st>>>(
                bQKV, bBE, bAp, s);
            gemm_mma<0,0><<<dim3(6, 49), 256, GSMEM, st>>>(
                bAp, pWp_ + wo * EW_PROJ, proj_b + wo * CDIM, bX,
                inX, pmap + s * NT, 768, 768);
            ln_pack_kernel<<<NT, 256, 0, st>>>(bX, n2_g + wo * CDIM, n2_b + wo * CDIM, bAp, nullptr);
            gemm_mma<1,1><<<dim3(24, 49), 256, GSMEM, st>>>(
                bAp, pWf1 + wo * EW_FC1, fc1_b + wo * 3072, (float*)bAp2,
                nullptr, nullptr, 3072, 768);
            gemm_mma<0,0><<<dim3(6, 49), 256, GSMEM, st>>>(
                bAp2, pWf2 + wo * EW_FC2, fc2_b + wo * CDIM, bX,
                bX, nullptr, 768, 3072);
        }
        ln_pack_kernel<<<NT, 256, 0, st>>>(bX, hln_g + br * CDIM, hln_b + br * CDIM, bAp, nullptr);
        gemm_mma<1,0><<<dim3(1, 49), 256, GSMEM, st>>>(
            bAp, pWc1 + br * EW_C1, c1_b + br * 64, bT3,
            nullptr, nullptr, 64, 768);
        conv2_kernel<<<(NT + 255) / 256, 256, 0, st>>>(bT3, c2_w + br * 2 * 64, c2_b + br * 2,
                                                       pO + (size_t)br * NT * 2);
    }

    cudaEventRecord(evJ, s1);
    cudaStreamWaitEvent(0, evJ, 0);
    final_kernel<<<(NT * 2 + 255) / 256, 256>>>(out);
}

// round 17
// speedup vs baseline: 2.2253x; 1.0293x over previous
#include <cuda_runtime.h>
#include <cuda_bf16.h>
#include <math.h>
#include <stdint.h>
#include <string.h>

#define B_    2
#define DD    16
#define HH    14
#define WWQ   14
#define CDIM  768
#define SP    (DD*HH*WWQ)      /* 3136 */
#define NT    (B_*SP)          /* 6272 tokens */
#define NWIN  392
#define BW    16
#define HEADS 24
#define HD    32
#define RPB_SZ 2535

/* packed weight element counts (bf16): [Wh | Wl], row stride 2K */
#define EW_QKV  (2304u*1536u)
#define EW_PROJ (768u*1536u)
#define EW_FC1  (3072u*1536u)
#define EW_FC2  (768u*6144u)
#define EW_C1   (128u*1536u)

/* ---------------- scratch ---------------- */
__device__ float g_Xs [NT*CDIM];                 /* shared transposed input */
__device__ float g_X  [2][NT*CDIM];
__device__ float g_QKV[2][NT*3*CDIM];
__device__ float g_T3 [2][NT*64];
__device__ float g_O  [2][NT*2];
__device__ int   g_map[2][NT];
__device__ float g_BiasE[4][(size_t)HEADS*NWIN*NWIN];   /* per (br,bl) expanded bias */
__device__ __nv_bfloat16 g_Wqkv [4*EW_QKV];
__device__ __nv_bfloat16 g_Wproj[4*EW_PROJ];
__device__ __nv_bfloat16 g_Wfc1 [4*EW_FC1];
__device__ __nv_bfloat16 g_Wfc2 [4*EW_FC2];
__device__ __nv_bfloat16 g_Wc1  [2*EW_C1];
__device__ __nv_bfloat16 g_Ap [2][(size_t)NT*1536];
__device__ __nv_bfloat16 g_Ap2[2][(size_t)NT*6144];

__device__ __forceinline__ float gelu_f(float x) {
    return 0.5f * x * (1.0f + erff(x * 0.70710678118654752f));
}
__device__ __forceinline__ uint32_t smem_u32(const void* p) {
    uint32_t a;
    asm("{ .reg .u64 t; cvta.to.shared.u64 t, %1; cvt.u32.u64 %0, t; }" : "=r"(a) : "l"(p));
    return a;
}
#define CP16(s, g) \
    asm volatile("cp.async.cg.shared.global [%0], [%1], 16;" :: "r"(s), "l"(g) : "memory")
#define CP_COMMIT() asm volatile("cp.async.commit_group;" ::: "memory")
#define CP_WAIT1()  asm volatile("cp.async.wait_group 1;" ::: "memory")
#define LDSM4(r, addr) \
    asm volatile("ldmatrix.sync.aligned.m8n8.x4.shared.b16 {%0,%1,%2,%3}, [%4];" \
        : "=r"((r)[0]), "=r"((r)[1]), "=r"((r)[2]), "=r"((r)[3]) : "r"(addr))
#define MMA16816(c, a, b0, b1) \
    asm volatile("mma.sync.aligned.m16n8k16.row.col.f32.bf16.bf16.f32 " \
        "{%0,%1,%2,%3}, {%4,%5,%6,%7}, {%8,%9}, {%0,%1,%2,%3};" \
        : "+f"((c)[0]), "+f"((c)[1]), "+f"((c)[2]), "+f"((c)[3]) \
        : "r"((a)[0]), "r"((a)[1]), "r"((a)[2]), "r"((a)[3]), "r"(b0), "r"(b1))
/* packed dual fp32 FMA: d = a*b + d (elementwise on 2 lanes) */
#define FMA2(d, a, b) \
    asm("fma.rn.f32x2 %0, %1, %2, %0;" : "+l"(d) : "l"(a), "l"(b))
#define DUP2(d, f) \
    asm("mov.b64 %0, {%1, %1};" : "=l"(d) : "f"(f))
#define UNPK2(lo, hi, v) \
    asm("mov.b64 {%0, %1}, %2;" : "=f"(lo), "=f"(hi) : "l"(v))

/* ---------------- window/roll index maps ---------------- */
__global__ void init_maps_kernel() {
    int wt = blockIdx.x * blockDim.x + threadIdx.x;
    if (wt >= NT) return;
    int win = wt / NWIN, n = wt % NWIN;
    int b = win >> 3, wr = win & 7;
    int wd = wr >> 2, wh = (wr >> 1) & 1, ww = wr & 1;
    int d0 = n / 49, r = n % 49, h0 = r / 7, w0 = r % 7;
    for (int s = 0; s < 2; s++) {
        int sd = s ? 4 : 0, sh = s ? 3 : 0, sw = s ? 3 : 0;
        int gd = (wd * 8 + d0 + sd) & 15;
        int gh = (wh * 7 + h0 + sh) % 14;
        int gw = (ww * 7 + w0 + sw) % 14;
        g_map[s][wt] = ((b * DD + gd) * HH + gh) * WWQ + gw;
    }
}

/* ---------------- expand rel-pos bias: biasE[h][n][m] = rpb[rpi[n][m]][h] ---------------- */
__global__ void bias_exp_kernel(const float* __restrict__ rpb, const int* __restrict__ rpi,
                                float* __restrict__ dst) {
    size_t idx = (size_t)blockIdx.x * 256 + threadIdx.x;
    if (idx >= (size_t)HEADS * NWIN * NWIN) return;
    int m = (int)(idx % NWIN);
    int rest = (int)(idx / NWIN);
    int n = rest % NWIN, h = rest / NWIN;
    dst[idx] = rpb[(size_t)rpi[n * NWIN + m] * HEADS + h];
}

/* ---------------- (B,C,D,H,W) -> (token, C) transpose ---------------- */
__global__ void transpose_in_kernel(const float* __restrict__ x, float* __restrict__ X) {
    __shared__ float tile[32][33];
    int b = blockIdx.z;
    int s0 = blockIdx.x * 32, c0 = blockIdx.y * 32;
    int tx = threadIdx.x, ty = threadIdx.y;
#pragma unroll
    for (int i = 0; i < 32; i += 8)
        tile[ty + i][tx] = x[((size_t)(b * CDIM + c0 + ty + i)) * SP + s0 + tx];
    __syncthreads();
#pragma unroll
    for (int i = 0; i < 32; i += 8)
        X[((size_t)(b * SP + s0 + ty + i)) * CDIM + c0 + tx] = tile[tx][ty + i];
}

/* ------- LayerNorm over C=768 -> packed bf16 [h | l], single-pass reduction ------- */
__global__ void ln_pack_kernel(const float* __restrict__ in, const float* __restrict__ gamma,
                               const float* __restrict__ beta, __nv_bfloat16* __restrict__ dst,
                               const int* __restrict__ map) {
    int t = blockIdx.x;
    int src = map ? map[t] : t;
    const float* row = in + (size_t)src * CDIM;
    __nv_bfloat16* orow = dst + (size_t)t * 1536;
    int tid = threadIdx.x;
    float v0 = row[tid], v1 = row[tid + 256], v2 = row[tid + 512];
    float s  = v0 + v1 + v2;
    float sq = v0 * v0 + v1 * v1 + v2 * v2;
    __shared__ float red[16];
#pragma unroll
    for (int o = 16; o; o >>= 1) {
        s  += __shfl_xor_sync(0xffffffffu, s, o);
        sq += __shfl_xor_sync(0xffffffffu, sq, o);
    }
    if ((tid & 31) == 0) { red[tid >> 5] = s; red[8 + (tid >> 5)] = sq; }
    __syncthreads();
    if (tid < 32) {
        float a = (tid < 8) ? red[tid] : 0.f;
        float b = (tid < 8) ? red[8 + tid] : 0.f;
#pragma unroll
        for (int o = 4; o; o >>= 1) {
            a += __shfl_xor_sync(0xffffffffu, a, o);
            b += __shfl_xor_sync(0xffffffffu, b, o);
        }
        if (tid == 0) { red[0] = a; red[8] = b; }
    }
    __syncthreads();
    float mu  = red[0] * (1.0f / CDIM);
    float var = red[8] * (1.0f / CDIM) - mu * mu;
    float inv = rsqrtf(var + 1e-5f);
#pragma unroll
    for (int q = 0; q < 3; q++) {
        int c = tid + q * 256;
        float vv = (q == 0 ? v0 : q == 1 ? v1 : v2);
        float v = (vv - mu) * inv * gamma[c] + beta[c];
        __nv_bfloat16 h = __float2bfloat16(v);
        __nv_bfloat16 l = __float2bfloat16(v - __bfloat162float(h));
        orow[c] = h;
        orow[768 + c] = l;
    }
}

/* ------- pack weights: fp32 [Nreal][K] -> bf16 [Npad][2K] = [Wh | Wl] ------- */
__global__ void pack_w_kernel(const float* __restrict__ src, __nv_bfloat16* __restrict__ dst,
                              int Nreal, int Npad, int K, size_t srcStride, size_t dstStride) {
    int z = blockIdx.z;
    src += (size_t)z * srcStride;
    dst += (size_t)z * dstStride;
    int idx = blockIdx.x * 256 + threadIdx.x;
    if (idx >= Npad * K) return;
    int k = idx % K, n = idx / K;
    float v = (n < Nreal) ? src[(size_t)n * K + k] : 0.f;
    __nv_bfloat16 h = __float2bfloat16(v);
    __nv_bfloat16 l = __float2bfloat16(v - __bfloat162float(h));
    size_t ro = (size_t)n * 2 * K;
    dst[ro + k] = h;
    dst[ro + K + k] = l;
}

/* ---------------- bf16 mma.sync GEMM (8 warps, 64x32 warp tile, 3-stage, 2 CTA/SM) ---------------- */
#define GSMEM (3 * 32768)
template<int ACT, int PACK>
__global__ void __launch_bounds__(256) gemm_mma(
    const __nv_bfloat16* __restrict__ A, const __nv_bfloat16* __restrict__ B,
    const float* __restrict__ bias, float* __restrict__ Out,
    const float* __restrict__ Res, const int* __restrict__ mapC,
    int Nreal, int K) {
    extern __shared__ char smraw[];
    uint32_t sbase = smem_u32(smraw);
    const int tid = threadIdx.x;
    const int nt = blockIdx.x, mt = blockIdx.y;
    const int KI3 = K >> 6;
    const int KT = 3 * KI3;
    const int K2 = 2 * K;

    const int lr0 = tid >> 3;
    const int lkg = tid & 7;
    const uint32_t lswz = (uint32_t)((lkg ^ (lr0 & 7)) * 16);
    const __nv_bfloat16* Ag = A + (size_t)(mt * 128 + lr0) * K2 + lkg * 8;
    const __nv_bfloat16* Bg = B + (size_t)(nt * 128 + lr0) * K2 + lkg * 8;
    uint32_t soffs[4];
#pragma unroll
    for (int i = 0; i < 4; i++) soffs[i] = (uint32_t)((lr0 + 32 * i) * 128) + lswz;

    const int lane = tid & 31, wid = tid >> 5;
    const int wm = wid & 1, wn = wid >> 1;
    const int arow = wm * 64 + (lane & 15);
    const int khalfA = lane >> 4;
    const int ar7 = arow & 7;
    uint32_t aoffs[4];
#pragma unroll
    for (int i = 0; i < 4; i++) aoffs[i] = (uint32_t)((arow + 16 * i) * 128);
    const int brow = wn * 32 + (lane & 7) + ((lane >> 4) << 3);
    const int kaddB = (lane >> 3) & 1;
    const int br7 = brow & 7;
    uint32_t boffs[2];
#pragma unroll
    for (int p = 0; p < 2; p++) boffs[p] = (uint32_t)(16384 + (brow + 16 * p) * 128);

    float acc[4][4][4];
#pragma unroll
    for (int i = 0; i < 4; i++)
#pragma unroll
        for (int j = 0; j < 4; j++)
#pragma unroll
            for (int r = 0; r < 4; r++) acc[i][j][r] = 0.f;

#pragma unroll
    for (int pl = 0; pl < 2; pl++) {
        uint32_t sa = sbase + pl * 32768, sb = sa + 16384;
        const __nv_bfloat16* ga = Ag + (size_t)pl * 64;
        const __nv_bfloat16* gb = Bg + (size_t)pl * 64;
#pragma unroll
        for (int i = 0; i < 4; i++) {
            CP16(sa + soffs[i], ga + (size_t)(32 * i) * K2);
            CP16(sb + soffs[i], gb + (size_t)(32 * i) * K2);
        }
        CP_COMMIT();
    }

    for (int kt = 0; kt < KT; kt++) {
        CP_WAIT1();
        __syncthreads();
        int s = kt - (kt / 3) * 3;
        int nk = kt + 2;
        if (nk < KT) {
            int s2 = nk - (nk / 3) * 3;
            int asl = (nk < KI3) ? nk : nk - KI3;
            int bsl = (nk < 2 * KI3) ? nk : nk - 2 * KI3;
            uint32_t sa = sbase + s2 * 32768, sb = sa + 16384;
            const __nv_bfloat16* ga = Ag + (size_t)asl * 64;
            const __nv_bfloat16* gb = Bg + (size_t)bsl * 64;
#pragma unroll
            for (int i = 0; i < 4; i++) {
                CP16(sa + soffs[i], ga + (size_t)(32 * i) * K2);
                CP16(sb + soffs[i], gb + (size_t)(32 * i) * K2);
            }
        }
        CP_COMMIT();
        uint32_t st = sbase + s * 32768;
#pragma unroll
        for (int ks = 0; ks < 4; ks++) {
            uint32_t a[4][4], b[2][4];
            uint32_t aswz = (uint32_t)(((2 * ks + khalfA) ^ ar7) * 16);
#pragma unroll
            for (int i = 0; i < 4; i++) LDSM4(a[i], st + aoffs[i] + aswz);
            uint32_t bswz = (uint32_t)(((2 * ks + kaddB) ^ br7) * 16);
#pragma unroll
            for (int p = 0; p < 2; p++) LDSM4(b[p], st + boffs[p] + bswz);
#pragma unroll
            for (int i = 0; i < 4; i++)
#pragma unroll
                for (int j = 0; j < 4; j++)
                    MMA16816(acc[i][j], a[i], b[j >> 1][(j & 1) * 2], b[j >> 1][(j & 1) * 2 + 1]);
        }
    }

    const int g = lane >> 2, tg = lane & 3;
#pragma unroll
    for (int i = 0; i < 4; i++) {
#pragma unroll
        for (int rh = 0; rh < 2; rh++) {
            int m = mt * 128 + wm * 64 + i * 16 + g + rh * 8;
            if (PACK == 0) {
                int orow = mapC ? mapC[m] : m;
                float* op = Out + (size_t)orow * Nreal;
                const float* rp = Res ? Res + (size_t)orow * Nreal : nullptr;
#pragma unroll
                for (int j = 0; j < 4; j++) {
                    int col = nt * 128 + wn * 32 + j * 8 + tg * 2;
                    if (col < Nreal) {
                        float v0 = acc[i][j][rh * 2 + 0] + bias[col];
                        float v1 = acc[i][j][rh * 2 + 1] + bias[col + 1];
                        if (ACT == 1) { v0 = gelu_f(v0); v1 = gelu_f(v1); }
                        if (rp) { v0 += rp[col]; v1 += rp[col + 1]; }
                        float2 o2 = make_float2(v0, v1);
                        *(float2*)(op + col) = o2;
                    }
                }
            } else {
                __nv_bfloat16* op = (__nv_bfloat16*)Out + (size_t)m * 2 * Nreal;
#pragma unroll
                for (int j = 0; j < 4; j++) {
                    int col = nt * 128 + wn * 32 + j * 8 + tg * 2;
                    float v0 = acc[i][j][rh * 2 + 0] + bias[col];
                    float v1 = acc[i][j][rh * 2 + 1] + bias[col + 1];
                    if (ACT == 1) { v0 = gelu_f(v0); v1 = gelu_f(v1); }
                    __nv_bfloat16 h0 = __float2bfloat16(v0);
                    __nv_bfloat16 h1 = __float2bfloat16(v1);
                    __nv_bfloat16 l0 = __float2bfloat16(v0 - __bfloat162float(h0));
                    __nv_bfloat16 l1 = __float2bfloat16(v1 - __bfloat162float(h1));
                    __nv_bfloat162 hh; hh.x = h0; hh.y = h1;
                    __nv_bfloat162 ll; ll.x = l0; ll.y = l1;
                    *(__nv_bfloat162*)(op + col) = hh;
                    *(__nv_bfloat162*)(op + Nreal + col) = ll;
                }
            }
        }
    }
}

/* ---------------- fused window attention v9: f32x2 QK/AV, masked-bias prefetch, STS.128 probs ---------------- */
#define ATTN2_FLOATS (3*NWIN*17*2 + 8*4*NWIN + NWIN)
__global__ void __launch_bounds__(256) attn2_kernel(
    const float* __restrict__ qkv, const float* __restrict__ biasE,
    __nv_bfloat16* __restrict__ aout, int shifted) {
    extern __shared__ float sm[];
    float2* Qs2 = (float2*)sm;
    float2* Ks2 = Qs2 + NWIN * 17;
    float2* Vs2 = Ks2 + NWIN * 17;
    float* probs = (float*)(Vs2 + NWIN * 17);
    int*   lbl   = (int*)(probs + 8 * 4 * NWIN);
    int head = blockIdx.x, win = blockIdx.y;
    int tid = threadIdx.x;
    const float scale = 0.17677669529663687f;

    for (int idx = tid; idx < NWIN * 16; idx += 256) {
        int n = idx >> 4, d2 = idx & 15;
        size_t base = ((size_t)(win * NWIN + n)) * (3 * CDIM) + head * HD + d2 * 2;
        float2 q = *(const float2*)(qkv + base);
        q.x *= scale; q.y *= scale;
        Qs2[n * 17 + d2] = q;
        Ks2[n * 17 + d2] = *(const float2*)(qkv + base + CDIM);
        Vs2[n * 17 + d2] = *(const float2*)(qkv + base + 2 * CDIM);
    }
    if (shifted) {
        int wr = win & 7, wd = wr >> 2, wh = (wr >> 1) & 1, ww = wr & 1;
        for (int n = tid; n < NWIN; n += 256) {
            int d0 = n / 49, r = n % 49, h0 = r / 7, w0 = r % 7;
            int gd = wd * 8 + d0, gh = wh * 7 + h0, gw = ww * 7 + w0;
            int rd = gd < 8 ? 0 : (gd < 12 ? 1 : 2);
            int rh = gh < 7 ? 0 : (gh < 11 ? 1 : 2);
            int rw = gw < 7 ? 0 : (gw < 11 ? 1 : 2);
            lbl[n] = rd * 9 + rh * 3 + rw;
        }
    }
    __syncthreads();

    int warp = tid >> 5, lane = tid & 31;
    float* pw = probs + warp * 4 * NWIN;
    const int d2l = lane & 15, mh = (lane >> 4) * 196;
    const float* biasH = biasE + (size_t)head * NWIN * NWIN;
    const int mlbl = shifted ? lbl[warp * 49] : 0;   /* all rows of this warp share a label row-set? no: per-row */

    for (int bt = 0; bt < 13; bt++) {
        int n0 = warp * 49 + bt * 4;
        int nmax = warp * 49 + 48;
        int nr[4];
#pragma unroll
        for (int r = 0; r < 4; r++) nr[r] = (n0 + r > nmax) ? nmax : n0 + r;

        /* ---- prefetch bias (+ folded shift mask) for 4 rows x 13 cols; overlaps QK ---- */
        float bv[4][13];
#pragma unroll
        for (int r = 0; r < 4; r++) {
            const float* brow_ = biasH + (size_t)nr[r] * NWIN;
            int nl = shifted ? lbl[nr[r]] : 0;
#pragma unroll
            for (int j = 0; j < 13; j++) {
                int m = j * 32 + lane;
                float b = (m < NWIN) ? __ldg(brow_ + m) : 0.f;
                if (shifted && m < NWIN && lbl[m] != nl) b -= 100.f;
                bv[r][j] = b;
            }
        }

        /* ---- QK with packed dual-fp32 FMA ---- */
        unsigned long long acc2[4][13];
#pragma unroll
        for (int r = 0; r < 4; r++)
#pragma unroll
            for (int j = 0; j < 13; j++) acc2[r][j] = 0ull;
#pragma unroll 4
        for (int d2 = 0; d2 < 16; d2++) {
            unsigned long long q[4];
#pragma unroll
            for (int r = 0; r < 4; r++)
                q[r] = *(const unsigned long long*)&Qs2[nr[r] * 17 + d2];
#pragma unroll
            for (int j = 0; j < 12; j++) {
                unsigned long long k2 = *(const unsigned long long*)&Ks2[(j * 32 + lane) * 17 + d2];
#pragma unroll
                for (int r = 0; r < 4; r++)
                    FMA2(acc2[r][j], q[r], k2);
            }
            if (lane < 8) {
                unsigned long long k2 = *(const unsigned long long*)&Ks2[(384 + lane) * 17 + d2];
#pragma unroll
                for (int r = 0; r < 4; r++)
                    FMA2(acc2[r][12], q[r], k2);
            }
        }

        /* ---- softmax: e-values to registers, then conflict-free STS.128 ---- */
        float invs[4];
        float ev[4][13];
#pragma unroll
        for (int r = 0; r < 4; r++) {
            float mx = -1e30f;
            float sv[13];
#pragma unroll
            for (int j = 0; j < 13; j++) {
                int m = j * 32 + lane;
                float s;
                if (m < NWIN) {
                    float2 a2;
                    memcpy(&a2, &acc2[r][j], 8);
                    s = a2.x + a2.y + bv[r][j];
                } else s = -3e38f;
                sv[j] = s;
                mx = fmaxf(mx, s);
            }
#pragma unroll
            for (int o = 16; o; o >>= 1) mx = fmaxf(mx, __shfl_xor_sync(0xffffffffu, mx, o));
            float sum = 0.f;
#pragma unroll
            for (int j = 0; j < 13; j++) {
                int m = j * 32 + lane;
                float e = (m < NWIN) ? __expf(sv[j] - mx) : 0.f;
                sum += e;
                ev[r][j] = e;
            }
#pragma unroll
            for (int o = 16; o; o >>= 1) sum += __shfl_xor_sync(0xffffffffu, sum, o);
            invs[r] = 1.f / sum;
        }
#pragma unroll
        for (int j = 0; j < 13; j++) {
            int m = j * 32 + lane;
            if (m < NWIN) {
                float4 pv = make_float4(ev[0][j], ev[1][j], ev[2][j], ev[3][j]);
                *(float4*)(pw + m * 4) = pv;
            }
        }
        __syncwarp();

        /* ---- AV with packed dual-fp32 FMA, LDS.128 probs ---- */
        unsigned long long ox01 = 0ull, ox23 = 0ull, oy01 = 0ull, oy23 = 0ull;
#pragma unroll 8
        for (int m = 0; m < 196; m++) {
            float2 v = Vs2[(m + mh) * 17 + d2l];
            ulonglong2 pp = *(const ulonglong2*)(pw + (m + mh) * 4);
            unsigned long long vx, vy;
            DUP2(vx, v.x);
            DUP2(vy, v.y);
            FMA2(ox01, pp.x, vx);
            FMA2(ox23, pp.y, vx);
            FMA2(oy01, pp.x, vy);
            FMA2(oy23, pp.y, vy);
        }
        float2 o[4];
        UNPK2(o[0].x, o[1].x, ox01);
        UNPK2(o[2].x, o[3].x, ox23);
        UNPK2(o[0].y, o[1].y, oy01);
        UNPK2(o[2].y, o[3].y, oy23);
#pragma unroll
        for (int r = 0; r < 4; r++) {
            o[r].x += __shfl_down_sync(0xffffffffu, o[r].x, 16);
            o[r].y += __shfl_down_sync(0xffffffffu, o[r].y, 16);
        }
        if (lane < 16) {
#pragma unroll
            for (int r = 0; r < 4; r++) {
                float vx = o[r].x * invs[r];
                float vy = o[r].y * invs[r];
                __nv_bfloat16 hx = __float2bfloat16(vx);
                __nv_bfloat16 hy = __float2bfloat16(vy);
                __nv_bfloat16 lx = __float2bfloat16(vx - __bfloat162float(hx));
                __nv_bfloat16 ly = __float2bfloat16(vy - __bfloat162float(hy));
                __nv_bfloat16* op = aout + (size_t)(win * NWIN + nr[r]) * 1536 + head * HD + d2l * 2;
                __nv_bfloat162 hh; hh.x = hx; hh.y = hy;
                __nv_bfloat162 ll; ll.x = lx; ll.y = ly;
                *(__nv_bfloat162*)op = hh;
                *(__nv_bfloat162*)(op + 768) = ll;
            }
        }
        __syncwarp();
    }
    (void)mlbl;
}

/* ---------------- conv2 (64 -> 2) + GELU ---------------- */
__global__ void conv2_kernel(const float* __restrict__ T3, const float* __restrict__ w,
                             const float* __restrict__ b, float* __restrict__ O) {
    int t = blockIdx.x * 256 + threadIdx.x;
    if (t >= NT) return;
    const float* r = T3 + (size_t)t * 64;
    float a0 = b[0], a1 = b[1];
#pragma unroll
    for (int k = 0; k < 64; k++) {
        float v = r[k];
        a0 += v * w[k];
        a1 += v * w[64 + k];
    }
    O[t * 2 + 0] = gelu_f(a0);
    O[t * 2 + 1] = gelu_f(a1);
}

__global__ void final_kernel(float* __restrict__ out) {
    int i = blockIdx.x * 256 + threadIdx.x;
    if (i >= NT * 2) return;
    int t = i >> 1, ch = i & 1;
    int b = t / SP, sp = t % SP;
    out[((size_t)(b * 2 + ch)) * SP + sp] = g_O[0][i] * g_O[1][i];
}

/* ---------------- host ---------------- */
extern "C" void kernel_launch(void* const* d_in, const int* in_sizes, int n_in,
                              void* d_out, int out_size) {
    const float* x      = (const float*)d_in[0];
    const float* n1_g   = (const float*)d_in[1];
    const float* n1_b   = (const float*)d_in[2];
    const float* qkv_w  = (const float*)d_in[3];
    const float* qkv_b  = (const float*)d_in[4];
    const float* proj_w = (const float*)d_in[5];
    const float* proj_b = (const float*)d_in[6];
    const float* rpb    = (const float*)d_in[7];
    const float* n2_g   = (const float*)d_in[8];
    const float* n2_b   = (const float*)d_in[9];
    const float* fc1_w  = (const float*)d_in[10];
    const float* fc1_b  = (const float*)d_in[11];
    const float* fc2_w  = (const float*)d_in[12];
    const float* fc2_b  = (const float*)d_in[13];
    const float* hln_g  = (const float*)d_in[14];
    const float* hln_b  = (const float*)d_in[15];
    const float* c1_w   = (const float*)d_in[16];
    const float* c1_b   = (const float*)d_in[17];
    const float* c2_w   = (const float*)d_in[18];
    const float* c2_b   = (const float*)d_in[19];
    const int*   rpi    = (const int*)d_in[20];
    float* out = (float*)d_out;

    float *pXs, *pX, *pQKV, *pT3, *pO, *pBiasE;
    int* pmap;
    __nv_bfloat16 *pWq, *pWp_, *pWf1, *pWf2, *pWc1, *pAp, *pAp2;
    cudaGetSymbolAddress((void**)&pXs,  g_Xs);
    cudaGetSymbolAddress((void**)&pX,   g_X);
    cudaGetSymbolAddress((void**)&pQKV, g_QKV);
    cudaGetSymbolAddress((void**)&pT3,  g_T3);
    cudaGetSymbolAddress((void**)&pO,   g_O);
    cudaGetSymbolAddress((void**)&pBiasE, g_BiasE);
    cudaGetSymbolAddress((void**)&pmap, g_map);
    cudaGetSymbolAddress((void**)&pWq,  g_Wqkv);
    cudaGetSymbolAddress((void**)&pWp_, g_Wproj);
    cudaGetSymbolAddress((void**)&pWf1, g_Wfc1);
    cudaGetSymbolAddress((void**)&pWf2, g_Wfc2);
    cudaGetSymbolAddress((void**)&pWc1, g_Wc1);
    cudaGetSymbolAddress((void**)&pAp,  g_Ap);
    cudaGetSymbolAddress((void**)&pAp2, g_Ap2);

    static cudaStream_t s1 = nullptr;
    static cudaEvent_t evF = nullptr, evJ = nullptr, evP0 = nullptr, evP1 = nullptr;
    if (!s1) {
        cudaStreamCreateWithFlags(&s1, cudaStreamNonBlocking);
        cudaEventCreateWithFlags(&evF, cudaEventDisableTiming);
        cudaEventCreateWithFlags(&evJ, cudaEventDisableTiming);
        cudaEventCreateWithFlags(&evP0, cudaEventDisableTiming);
        cudaEventCreateWithFlags(&evP1, cudaEventDisableTiming);
    }

    const int attn_smem = ATTN2_FLOATS * 4;
    cudaFuncSetAttribute(attn2_kernel, cudaFuncAttributeMaxDynamicSharedMemorySize, attn_smem);
    cudaFuncSetAttribute(gemm_mma<0,0>, cudaFuncAttributeMaxDynamicSharedMemorySize, GSMEM);
    cudaFuncSetAttribute(gemm_mma<1,0>, cudaFuncAttributeMaxDynamicSharedMemorySize, GSMEM);
    cudaFuncSetAttribute(gemm_mma<1,1>, cudaFuncAttributeMaxDynamicSharedMemorySize, GSMEM);

    cudaEventRecord(evF, 0);
    cudaStreamWaitEvent(s1, evF, 0);

    const int biasE_grid = (int)(((size_t)HEADS * NWIN * NWIN + 255) / 256);
    const size_t BE_SZ = (size_t)HEADS * NWIN * NWIN;

    /* setup phase, split across both streams */
    init_maps_kernel<<<(NT + 255) / 256, 256>>>();
    transpose_in_kernel<<<dim3(SP / 32, CDIM / 32, B_), dim3(32, 8)>>>(x, pXs);
    pack_w_kernel<<<dim3((2304 * 768 + 255) / 256, 1, 4), 256>>>(
        qkv_w, pWq, 2304, 2304, 768, (size_t)2304 * 768, (size_t)EW_QKV);
    pack_w_kernel<<<dim3((768 * 768 + 255) / 256, 1, 4), 256>>>(
        proj_w, pWp_, 768, 768, 768, (size_t)768 * 768, (size_t)EW_PROJ);
    pack_w_kernel<<<dim3((128 * 768 + 255) / 256, 1, 2), 256>>>(
        c1_w, pWc1, 64, 128, 768, (size_t)64 * 768, (size_t)EW_C1);
    bias_exp_kernel<<<biasE_grid, 256>>>(rpb + 0 * RPB_SZ * HEADS, rpi, pBiasE + 0 * BE_SZ);
    bias_exp_kernel<<<biasE_grid, 256>>>(rpb + 1 * RPB_SZ * HEADS, rpi, pBiasE + 1 * BE_SZ);
    cudaEventRecord(evP0, 0);
    pack_w_kernel<<<dim3((3072 * 768 + 255) / 256, 1, 4), 256, 0, s1>>>(
        fc1_w, pWf1, 3072, 3072, 768, (size_t)3072 * 768, (size_t)EW_FC1);
    pack_w_kernel<<<dim3((768 * 3072 + 255) / 256, 1, 4), 256, 0, s1>>>(
        fc2_w, pWf2, 768, 768, 3072, (size_t)768 * 3072, (size_t)EW_FC2);
    bias_exp_kernel<<<biasE_grid, 256, 0, s1>>>(rpb + 2 * RPB_SZ * HEADS, rpi, pBiasE + 2 * BE_SZ);
    bias_exp_kernel<<<biasE_grid, 256, 0, s1>>>(rpb + 3 * RPB_SZ * HEADS, rpi, pBiasE + 3 * BE_SZ);
    cudaEventRecord(evP1, s1);
    cudaStreamWaitEvent(0, evP1, 0);
    cudaStreamWaitEvent(s1, evP0, 0);

    for (int br = 0; br < 2; br++) {
        cudaStream_t st = br ? s1 : (cudaStream_t)0;
        float* bX   = pX   + (size_t)br * NT * CDIM;
        float* bQKV = pQKV + (size_t)br * NT * 3 * CDIM;
        float* bT3  = pT3  + (size_t)br * NT * 64;
        __nv_bfloat16* bAp  = pAp  + (size_t)br * NT * 1536;
        __nv_bfloat16* bAp2 = pAp2 + (size_t)br * NT * 6144;

        for (int bl = 0; bl < 2; bl++) {
            int s = bl;
            size_t wo = (size_t)(br * 2 + bl);
            const float* inX  = (bl == 0) ? pXs : bX;   /* block0 reads shared transpose */
            float* bBE = pBiasE + wo * BE_SZ;
            ln_pack_kernel<<<NT, 256, 0, st>>>(inX, n1_g + wo * CDIM, n1_b + wo * CDIM, bAp, pmap + s * NT);
            gemm_mma<0,0><<<dim3(18, 49), 256, GSMEM, st>>>(
                bAp, pWq + wo * EW_QKV, qkv_b + wo * 2304, bQKV,
                nullptr, nullptr, 2304, 768);
            attn2_kernel<<<dim3(HEADS, BW), 256, attn_smem, st>>>(
                bQKV, bBE, bAp, s);
            gemm_mma<0,0><<<dim3(6, 49), 256, GSMEM, st>>>(
                bAp, pWp_ + wo * EW_PROJ, proj_b + wo * CDIM, bX,
                inX, pmap + s * NT, 768, 768);
            ln_pack_kernel<<<NT, 256, 0, st>>>(bX, n2_g + wo * CDIM, n2_b + wo * CDIM, bAp, nullptr);
            gemm_mma<1,1><<<dim3(24, 49), 256, GSMEM, st>>>(
                bAp, pWf1 + wo * EW_FC1, fc1_b + wo * 3072, (float*)bAp2,
                nullptr, nullptr, 3072, 768);
            gemm_mma<0,0><<<dim3(6, 49), 256, GSMEM, st>>>(
                bAp2, pWf2 + wo * EW_FC2, fc2_b + wo * CDIM, bX,
                bX, nullptr, 768, 3072);
        }
        ln_pack_kernel<<<NT, 256, 0, st>>>(bX, hln_g + br * CDIM, hln_b + br * CDIM, bAp, nullptr);
        gemm_mma<1,0><<<dim3(1, 49), 256, GSMEM, st>>>(
            bAp, pWc1 + br * EW_C1, c1_b + br * 64, bT3,
            nullptr, nullptr, 64, 768);
        conv2_kernel<<<(NT + 255) / 256, 256, 0, st>>>(bT3, c2_w + br * 2 * 64, c2_b + br * 2,
                                                       pO + (size_t)br * NT * 2);
    }

    cudaEventRecord(evJ, s1);
    cudaStreamWaitEvent(0, evJ, 0);
    final_kernel<<<(NT * 2 + 255) / 256, 256>>>(out);
}